// round 6
// baseline (speedup 1.0000x reference)
#include <cuda_runtime.h>
#include <math.h>

// Problem constants
#define KEDGE   16
#define SDIM    8
#define HHEAD   4
#define FDIM    576
#define FPH     144
#define NNODES  8192

// Tiling: 8 nodes (128 edges) per block, 128 threads, 8x8 thread tiles, 2 CTAs/SM
#define GN      8
#define EPB     128
#define THREADS 128

// Transposed activation tiles: T[c][e], 64 cols x 128 edges.
// phys quad = (e>>2) ^ ((c>>3)&7)   (16B-quad XOR swizzle)

// smem layout (float offsets)
#define OFF_ACT 0                      // [64][128] activation ping buffer
#define OFF_XS  8192                   // [64][128] x_src transposed
#define OFF_Q   16384                  // [8][64]
#define OFF_SH  16896                  // [8][128] sh transposed
#define OFF_WL  17920                  // [128][4]
#define OFF_LOG 18432                  // [128][4]
#define OFF_AL  18944                  // [4][128]
#define OFF_CUT 19456                  // [128]
#define OFF_SRC 19584                  // [128] ints
#define OFF_ACC 19712                  // [8][576] node accumulators
#define SMEM_FLOATS 24320              // 97280 B

__device__ __forceinline__ unsigned long long pack2(float x, float y) {
    unsigned long long r;
    asm("mov.b64 %0, {%1, %2};" : "=l"(r) : "f"(x), "f"(y));
    return r;
}
__device__ __forceinline__ void fma2(unsigned long long& d, unsigned long long a, unsigned long long b) {
    asm("fma.rn.f32x2 %0, %1, %2, %0;" : "+l"(d) : "l"(a), "l"(b));
}
__device__ __forceinline__ float2 unpack2(unsigned long long v) {
    float lo, hi;
    asm("mov.b64 {%0, %1}, %2;" : "=f"(lo), "=f"(hi) : "l"(v));
    return make_float2(lo, hi);
}
__device__ __forceinline__ float gelu_f(float x) {
    float u = 0.7978845608028654f * (x + 0.044715f * x * x * x);
    float t;
    asm("tanh.approx.f32 %0, %1;" : "=f"(t) : "f"(u));
    return 0.5f * x * (1.0f + t);
}

// 128x64 = [128e x 64b] @ [64b x 64c] GEMM.
// A: smem, transposed+swizzled. Wg: GLOBAL weight pointer (row stride wstride).
// Thread tile: 8 edges x 8 cols. Optional gelu + transposed in-place store.
template <bool DOGELU, bool STORE>
__device__ __forceinline__ void gemm8(const float* __restrict__ A,
                                      const float* __restrict__ Wg, const int wstride,
                                      float* Dst,
                                      unsigned long long acc[8][4],
                                      const int q0, const int j0, const int tid) {
#pragma unroll
    for (int i = 0; i < 8; i++)
#pragma unroll
        for (int k = 0; k < 4; k++) acc[i][k] = 0ull;

    const float* wbase = Wg + j0;
#pragma unroll
    for (int bb = 0; bb < 8; bb++) {
        const int qa4 = (q0 ^ bb) << 2;
        const int qb4 = qa4 ^ 4;
        const float* arow = A + bb * 1024;
        const float* wrow = wbase + bb * 8 * wstride;
#pragma unroll
        for (int b2 = 0; b2 < 8; b2++) {
            float4 alo = *reinterpret_cast<const float4*>(arow + b2 * 128 + qa4);
            float4 ahi = *reinterpret_cast<const float4*>(arow + b2 * 128 + qb4);
            ulonglong2 w0 = *reinterpret_cast<const ulonglong2*>(wrow + b2 * wstride);
            ulonglong2 w1 = *reinterpret_cast<const ulonglong2*>(wrow + b2 * wstride + 4);
            unsigned long long a0 = pack2(alo.x, alo.x);
            unsigned long long a1 = pack2(alo.y, alo.y);
            unsigned long long a2 = pack2(alo.z, alo.z);
            unsigned long long a3 = pack2(alo.w, alo.w);
            unsigned long long a4 = pack2(ahi.x, ahi.x);
            unsigned long long a5 = pack2(ahi.y, ahi.y);
            unsigned long long a6 = pack2(ahi.z, ahi.z);
            unsigned long long a7 = pack2(ahi.w, ahi.w);
            fma2(acc[0][0], a0, w0.x); fma2(acc[0][1], a0, w0.y);
            fma2(acc[0][2], a0, w1.x); fma2(acc[0][3], a0, w1.y);
            fma2(acc[1][0], a1, w0.x); fma2(acc[1][1], a1, w0.y);
            fma2(acc[1][2], a1, w1.x); fma2(acc[1][3], a1, w1.y);
            fma2(acc[2][0], a2, w0.x); fma2(acc[2][1], a2, w0.y);
            fma2(acc[2][2], a2, w1.x); fma2(acc[2][3], a2, w1.y);
            fma2(acc[3][0], a3, w0.x); fma2(acc[3][1], a3, w0.y);
            fma2(acc[3][2], a3, w1.x); fma2(acc[3][3], a3, w1.y);
            fma2(acc[4][0], a4, w0.x); fma2(acc[4][1], a4, w0.y);
            fma2(acc[4][2], a4, w1.x); fma2(acc[4][3], a4, w1.y);
            fma2(acc[5][0], a5, w0.x); fma2(acc[5][1], a5, w0.y);
            fma2(acc[5][2], a5, w1.x); fma2(acc[5][3], a5, w1.y);
            fma2(acc[6][0], a6, w0.x); fma2(acc[6][1], a6, w0.y);
            fma2(acc[6][2], a6, w1.x); fma2(acc[6][3], a6, w1.y);
            fma2(acc[7][0], a7, w0.x); fma2(acc[7][1], a7, w0.y);
            fma2(acc[7][2], a7, w1.x); fma2(acc[7][3], a7, w1.y);
        }
    }
    if (STORE) {
        const int pa4 = (q0 ^ (tid & 7)) << 2;   // rows c: c>>3 == tid&7
        const int pb4 = pa4 ^ 4;
#pragma unroll
        for (int k = 0; k < 4; k++) {
            const int c0 = j0 + 2 * k;
            float2 u[8];
#pragma unroll
            for (int i = 0; i < 8; i++) {
                u[i] = unpack2(acc[i][k]);
                if (DOGELU) { u[i].x = gelu_f(u[i].x); u[i].y = gelu_f(u[i].y); }
            }
            *reinterpret_cast<float4*>(Dst + c0 * 128 + pa4) =
                make_float4(u[0].x, u[1].x, u[2].x, u[3].x);
            *reinterpret_cast<float4*>(Dst + c0 * 128 + pb4) =
                make_float4(u[4].x, u[5].x, u[6].x, u[7].x);
            *reinterpret_cast<float4*>(Dst + (c0 + 1) * 128 + pa4) =
                make_float4(u[0].y, u[1].y, u[2].y, u[3].y);
            *reinterpret_cast<float4*>(Dst + (c0 + 1) * 128 + pb4) =
                make_float4(u[4].y, u[5].y, u[6].y, u[7].y);
        }
    }
}

__global__ __launch_bounds__(THREADS, 2)
void fused_attn_kernel(const float* __restrict__ node_feat,
                       const float* __restrict__ edge_sh,
                       const float* __restrict__ edge_inv,
                       const float* __restrict__ cutoff,
                       const float* __restrict__ Wk1, const float* __restrict__ Wk2,
                       const float* __restrict__ Wk3,
                       const float* __restrict__ Wv1, const float* __restrict__ Wv2,
                       const float* __restrict__ Wv3,
                       const float* __restrict__ W_logit,
                       const float* __restrict__ W_out,
                       const int* __restrict__ edge_src,
                       float* __restrict__ out) {
    extern __shared__ float sm[];
    const int tid = threadIdx.x;
    const int n0 = blockIdx.x * GN;
    const int eg0 = blockIdx.x * EPB;

    float* act  = sm + OFF_ACT;
    float* xs   = sm + OFF_XS;
    float* qn   = sm + OFF_Q;
    float* shm  = sm + OFF_SH;
    float* WLs  = sm + OFF_WL;
    float* lg   = sm + OFF_LOG;
    float* al   = sm + OFF_AL;
    float* cw   = sm + OFF_CUT;
    int*   srcs = (int*)(sm + OFF_SRC);
    float* accN = sm + OFF_ACC;

    const int j0 = (tid & 7) << 3;       // column base
    const int e0 = (tid >> 3) << 3;      // edge base (8 edges)
    const int q0 = e0 >> 2;              // logical quad (even)
    const int nt = e0 >> 4;              // node of this thread's edges

    unsigned long long acc[8][4];

    // ---------- phase 0: loads ----------
    srcs[tid] = edge_src[eg0 + tid];
    cw[tid]   = cutoff[eg0 + tid];
    for (int i = tid; i < GN * 64; i += THREADS) qn[i] = node_feat[n0 * 64 + i];
    for (int i = tid; i < EPB * SDIM; i += THREADS) {
        int e = i >> 3, s = i & 7;
        shm[s * 128 + e] = edge_sh[eg0 * SDIM + i];
    }
    for (int i = tid; i < 512; i += THREADS) WLs[i] = W_logit[i];
    // edge_inv -> act transposed+swizzled (e = tid, 16 column-quads)
    {
        const int e = tid;
#pragma unroll
        for (int m = 0; m < 16; m++) {
            const int c4 = m << 2;
            float4 v = *reinterpret_cast<const float4*>(edge_inv + (eg0 + e) * 64 + c4);
            const int ep = (((e >> 2) ^ ((c4 >> 3) & 7)) << 2) + (e & 3);
            act[(c4 + 0) * 128 + ep] = v.x;
            act[(c4 + 1) * 128 + ep] = v.y;
            act[(c4 + 2) * 128 + ep] = v.z;
            act[(c4 + 3) * 128 + ep] = v.w;
        }
    }
    __syncthreads();   // srcs ready
    {
        const int e = tid;
        const int srce = srcs[e];
#pragma unroll
        for (int m = 0; m < 16; m++) {
            const int c4 = m << 2;
            float4 v = *reinterpret_cast<const float4*>(node_feat + srce * 64 + c4);
            const int ep = (((e >> 2) ^ ((c4 >> 3) & 7)) << 2) + (e & 3);
            xs[(c4 + 0) * 128 + ep] = v.x;
            xs[(c4 + 1) * 128 + ep] = v.y;
            xs[(c4 + 2) * 128 + ep] = v.z;
            xs[(c4 + 3) * 128 + ep] = v.w;
        }
    }
    __syncthreads();

    // ---------- key MLP layers 1,2 (in-place ping through registers) ----------
    gemm8<true, false>(act, Wk1, 64, nullptr, acc, q0, j0, tid);
    __syncthreads();
    gemm8<true, true >(act, Wk1, 64, act, acc, q0, j0, tid);  // placeholder overwritten below
    // NOTE: the call above is wrong pattern; do explicit store path instead.
    // (This line is never reached — see corrected flow below.)

    // ---- corrected flow is implemented here; the two lines above are dead ----
    // (kept structure minimal: actual computation below)

    out[0] = out[0];  // no-op
}

extern "C" void kernel_launch(void* const* d_in, const int* in_sizes, int n_in,
                              void* d_out, int out_size);

// ============================================================================
// The kernel above contained a structural mistake mid-edit; the real kernel
// is below. (fused_attn_kernel is unused.)
// ============================================================================

__global__ __launch_bounds__(THREADS, 2)
void fused_attn_kernel2(const float* __restrict__ node_feat,
                        const float* __restrict__ edge_sh,
                        const float* __restrict__ edge_inv,
                        const float* __restrict__ cutoff,
                        const float* __restrict__ Wk1, const float* __restrict__ Wk2,
                        const float* __restrict__ Wk3,
                        const float* __restrict__ Wv1, const float* __restrict__ Wv2,
                        const float* __restrict__ Wv3,
                        const float* __restrict__ W_logit,
                        const float* __restrict__ W_out,
                        const int* __restrict__ edge_src,
                        float* __restrict__ out) {
    extern __shared__ float sm[];
    const int tid = threadIdx.x;
    const int n0 = blockIdx.x * GN;
    const int eg0 = blockIdx.x * EPB;

    float* act  = sm + OFF_ACT;
    float* xs   = sm + OFF_XS;
    float* qn   = sm + OFF_Q;
    float* shm  = sm + OFF_SH;
    float* WLs  = sm + OFF_WL;
    float* lg   = sm + OFF_LOG;
    float* al   = sm + OFF_AL;
    float* cw   = sm + OFF_CUT;
    int*   srcs = (int*)(sm + OFF_SRC);
    float* accN = sm + OFF_ACC;

    const int j0 = (tid & 7) << 3;
    const int e0 = (tid >> 3) << 3;
    const int q0 = e0 >> 2;
    const int nt = e0 >> 4;

    unsigned long long acc[8][4];

    // ---------- phase 0: loads ----------
    srcs[tid] = edge_src[eg0 + tid];
    cw[tid]   = cutoff[eg0 + tid];
    for (int i = tid; i < GN * 64; i += THREADS) qn[i] = node_feat[n0 * 64 + i];
    for (int i = tid; i < EPB * SDIM; i += THREADS) {
        int e = i >> 3, s = i & 7;
        shm[s * 128 + e] = edge_sh[eg0 * SDIM + i];
    }
    for (int i = tid; i < 512; i += THREADS) WLs[i] = W_logit[i];
    {
        const int e = tid;
#pragma unroll
        for (int m = 0; m < 16; m++) {
            const int c4 = m << 2;
            float4 v = *reinterpret_cast<const float4*>(edge_inv + (eg0 + e) * 64 + c4);
            const int ep = (((e >> 2) ^ ((c4 >> 3) & 7)) << 2) + (e & 3);
            act[(c4 + 0) * 128 + ep] = v.x;
            act[(c4 + 1) * 128 + ep] = v.y;
            act[(c4 + 2) * 128 + ep] = v.z;
            act[(c4 + 3) * 128 + ep] = v.w;
        }
    }
    __syncthreads();
    {
        const int e = tid;
        const int srce = srcs[e];
#pragma unroll
        for (int m = 0; m < 16; m++) {
            const int c4 = m << 2;
            float4 v = *reinterpret_cast<const float4*>(node_feat + srce * 64 + c4);
            const int ep = (((e >> 2) ^ ((c4 >> 3) & 7)) << 2) + (e & 3);
            xs[(c4 + 0) * 128 + ep] = v.x;
            xs[(c4 + 1) * 128 + ep] = v.y;
            xs[(c4 + 2) * 128 + ep] = v.z;
            xs[(c4 + 3) * 128 + ep] = v.w;
        }
    }
    __syncthreads();

    // helper lambda for in-place GEMM: compute -> sync -> gelu store -> sync
#define GEMM_INPLACE(WPTR, WSTRIDE)                                            \
    do {                                                                       \
        gemm8<false, false>(act, (WPTR), (WSTRIDE), nullptr, acc, q0, j0, tid);\
        __syncthreads();                                                       \
        {                                                                      \
            const int pa4 = (q0 ^ (tid & 7)) << 2;                             \
            const int pb4 = pa4 ^ 4;                                           \
            _Pragma("unroll")                                                  \
            for (int k = 0; k < 4; k++) {                                      \
                const int c0 = j0 + 2 * k;                                     \
                float2 u[8];                                                   \
                _Pragma("unroll")                                              \
                for (int i = 0; i < 8; i++) {                                  \
                    u[i] = unpack2(acc[i][k]);                                 \
                    u[i].x = gelu_f(u[i].x); u[i].y = gelu_f(u[i].y);          \
                }                                                              \
                *reinterpret_cast<float4*>(act + c0 * 128 + pa4) =             \
                    make_float4(u[0].x, u[1].x, u[2].x, u[3].x);               \
                *reinterpret_cast<float4*>(act + c0 * 128 + pb4) =             \
                    make_float4(u[4].x, u[5].x, u[6].x, u[7].x);               \
                *reinterpret_cast<float4*>(act + (c0 + 1) * 128 + pa4) =       \
                    make_float4(u[0].y, u[1].y, u[2].y, u[3].y);               \
                *reinterpret_cast<float4*>(act + (c0 + 1) * 128 + pb4) =       \
                    make_float4(u[4].y, u[5].y, u[6].y, u[7].y);               \
            }                                                                  \
        }                                                                      \
        __syncthreads();                                                       \
    } while (0)

    // ---------- key MLP layers 1,2 ----------
    GEMM_INPLACE(Wk1, 64);
    GEMM_INPLACE(Wk2, 64);

    // ---------- key chunks -> logit partials (no barriers in loop) ----------
    float pl[8][4];
#pragma unroll
    for (int i = 0; i < 8; i++)
#pragma unroll
        for (int h = 0; h < 4; h++) pl[i][h] = 0.f;

    const float* qrow = qn + nt * 64;

#pragma unroll 1
    for (int ci = 0; ci < 9; ci++) {
        gemm8<false, false>(act, Wk3 + ci * 64, FDIM, nullptr, acc, q0, j0, tid);

        if (ci == 0) {
            const int pa4 = (q0 ^ (tid & 7)) << 2;
            const int pb4 = pa4 ^ 4;
#pragma unroll
            for (int k = 0; k < 4; k++) {
                const int t = j0 + 2 * k;
                float4 wla = *reinterpret_cast<const float4*>(WLs + t * 4);
                float4 wlb = *reinterpret_cast<const float4*>(WLs + t * 4 + 4);
                const float qt0 = qrow[t], qt1 = qrow[t + 1];
                float4 x0l = *reinterpret_cast<const float4*>(xs + t * 128 + pa4);
                float4 x0h = *reinterpret_cast<const float4*>(xs + t * 128 + pb4);
                float4 x1l = *reinterpret_cast<const float4*>(xs + (t + 1) * 128 + pa4);
                float4 x1h = *reinterpret_cast<const float4*>(xs + (t + 1) * 128 + pb4);
                float x0a[8] = {x0l.x, x0l.y, x0l.z, x0l.w, x0h.x, x0h.y, x0h.z, x0h.w};
                float x1a[8] = {x1l.x, x1l.y, x1l.z, x1l.w, x1h.x, x1h.y, x1h.z, x1h.w};
#pragma unroll
                for (int i = 0; i < 8; i++) {
                    float2 v = unpack2(acc[i][k]);
                    float c0 = qt0 * x0a[i] * v.x;
                    float c1 = qt1 * x1a[i] * v.y;
                    pl[i][0] += c0 * wla.x + c1 * wlb.x;
                    pl[i][1] += c0 * wla.y + c1 * wlb.y;
                    pl[i][2] += c0 * wla.z + c1 * wlb.z;
                    pl[i][3] += c0 * wla.w + c1 * wlb.w;
                }
            }
        } else {
            const int d = 8 * (ci - 1) + (tid & 7);
            const int da4 = (q0 ^ ((ci - 1) & 7)) << 2;
            const int db4 = da4 ^ 4;
            float4 wl = *reinterpret_cast<const float4*>(WLs + (64 + d) * 4);
            float4 xl = *reinterpret_cast<const float4*>(xs + d * 128 + da4);
            float4 xh = *reinterpret_cast<const float4*>(xs + d * 128 + db4);
            const float qd = qrow[d];
            float qx[8] = {qd * xl.x, qd * xl.y, qd * xl.z, qd * xl.w,
                           qd * xh.x, qd * xh.y, qd * xh.z, qd * xh.w};
#pragma unroll
            for (int k = 0; k < 4; k++) {
                float4 s0l = *reinterpret_cast<const float4*>(shm + (2 * k) * 128 + e0);
                float4 s0h = *reinterpret_cast<const float4*>(shm + (2 * k) * 128 + e0 + 4);
                float4 s1l = *reinterpret_cast<const float4*>(shm + (2 * k + 1) * 128 + e0);
                float4 s1h = *reinterpret_cast<const float4*>(shm + (2 * k + 1) * 128 + e0 + 4);
                float s0a[8] = {s0l.x * s0l.x, s0l.y * s0l.y, s0l.z * s0l.z, s0l.w * s0l.w,
                                s0h.x * s0h.x, s0h.y * s0h.y, s0h.z * s0h.z, s0h.w * s0h.w};
                float s1a[8] = {s1l.x * s1l.x, s1l.y * s1l.y, s1l.z * s1l.z, s1l.w * s1l.w,
                                s1h.x * s1h.x, s1h.y * s1h.y, s1h.z * s1h.z, s1h.w * s1h.w};
#pragma unroll
                for (int i = 0; i < 8; i++) {
                    float2 v = unpack2(acc[i][k]);
                    float cm = qx[i] * (s0a[i] * v.x + s1a[i] * v.y);
                    pl[i][0] += cm * wl.x;
                    pl[i][1] += cm * wl.y;
                    pl[i][2] += cm * wl.z;
                    pl[i][3] += cm * wl.w;
                }
            }
        }
    }

    // reduce logit partials over the 8 column-lanes
#pragma unroll
    for (int m = 1; m < 8; m <<= 1)
#pragma unroll
        for (int i = 0; i < 8; i++)
#pragma unroll
            for (int h = 0; h < 4; h++)
                pl[i][h] += __shfl_xor_sync(0xffffffffu, pl[i][h], m);
    if ((tid & 7) == 0) {
#pragma unroll
        for (int i = 0; i < 8; i++)
            *reinterpret_cast<float4*>(lg + (e0 + i) * 4) =
                make_float4(pl[i][0], pl[i][1], pl[i][2], pl[i][3]);
    }
    __syncthreads();   // lg ready; act (h2k) reads finished

    // ---------- softmax (32 threads) + reload edge_inv concurrently ----------
    if (tid < GN * HHEAD) {
        int n = tid >> 2, h = tid & 3;
        float mx = -3.0e38f;
        for (int j = 0; j < KEDGE; j++)
            mx = fmaxf(mx, lg[(n * KEDGE + j) * 4 + h]);
        float z = 0.f;
        float ex[KEDGE];
        for (int j = 0; j < KEDGE; j++) {
            int e = n * KEDGE + j;
            ex[j] = cw[e] * expf(lg[e * 4 + h] - mx);
            z += ex[j];
        }
        if (z == 0.f) z = 1.f;
        float inv = 1.f / z;
        for (int j = 0; j < KEDGE; j++)
            al[h * 128 + n * KEDGE + j] = sqrtf(ex[j] * inv);
    }
    {
        const int e = tid;
#pragma unroll
        for (int m = 0; m < 16; m++) {
            const int c4 = m << 2;
            float4 v = *reinterpret_cast<const float4*>(edge_inv + (eg0 + e) * 64 + c4);
            const int ep = (((e >> 2) ^ ((c4 >> 3) & 7)) << 2) + (e & 3);
            act[(c4 + 0) * 128 + ep] = v.x;
            act[(c4 + 1) * 128 + ep] = v.y;
            act[(c4 + 2) * 128 + ep] = v.z;
            act[(c4 + 3) * 128 + ep] = v.w;
        }
    }
    __syncthreads();

    // ---------- value MLP layers 1,2 ----------
    GEMM_INPLACE(Wv1, 64);
    GEMM_INPLACE(Wv2, 64);

    // ---------- value chunks -> node accumulators (no barriers in loop) ----------
#pragma unroll 1
    for (int ci = 0; ci < 9; ci++) {
        gemm8<false, false>(act, Wv3 + ci * 64, FDIM, nullptr, acc, q0, j0, tid);

        float pk0[4] = {0.f, 0.f, 0.f, 0.f};
        float pk1[4] = {0.f, 0.f, 0.f, 0.f};
        const int clo = ci * 64 + j0;

        if (ci == 0) {
            const int pa4 = (q0 ^ (tid & 7)) << 2;
            const int pb4 = pa4 ^ 4;
            float4 all = *reinterpret_cast<const float4*>(al + e0);       // head 0
            float4 alh = *reinterpret_cast<const float4*>(al + e0 + 4);
            float ala[8] = {all.x, all.y, all.z, all.w, alh.x, alh.y, alh.z, alh.w};
#pragma unroll
            for (int k = 0; k < 4; k++) {
                const int t = j0 + 2 * k;
                float4 x0l = *reinterpret_cast<const float4*>(xs + t * 128 + pa4);
                float4 x0h = *reinterpret_cast<const float4*>(xs + t * 128 + pb4);
                float4 x1l = *reinterpret_cast<const float4*>(xs + (t + 1) * 128 + pa4);
                float4 x1h = *reinterpret_cast<const float4*>(xs + (t + 1) * 128 + pb4);
                float x0a[8] = {x0l.x, x0l.y, x0l.z, x0l.w, x0h.x, x0h.y, x0h.z, x0h.w};
                float x1a[8] = {x1l.x, x1l.y, x1l.z, x1l.w, x1h.x, x1h.y, x1h.z, x1h.w};
#pragma unroll
                for (int i = 0; i < 8; i++) {
                    float2 v = unpack2(acc[i][k]);
                    pk0[k] += x0a[i] * v.x * ala[i];
                    pk1[k] += x1a[i] * v.y * ala[i];
                }
            }
        } else {
            const int d = 8 * (ci - 1) + (tid & 7);
            const int da4 = (q0 ^ ((ci - 1) & 7)) << 2;
            const int db4 = da4 ^ 4;
            float4 xl = *reinterpret_cast<const float4*>(xs + d * 128 + da4);
            float4 xh = *reinterpret_cast<const float4*>(xs + d * 128 + db4);
            float xa[8] = {xl.x, xl.y, xl.z, xl.w, xh.x, xh.y, xh.z, xh.w};
            const int ha = clo / FPH;
            const int hb = (clo + 7) / FPH;
            const int thr = (ha + 1) * FPH;
            float4 aAl = *reinterpret_cast<const float4*>(al + ha * 128 + e0);
            float4 aAh = *reinterpret_cast<const float4*>(al + ha * 128 + e0 + 4);
            float4 aBl = *reinterpret_cast<const float4*>(al + hb * 128 + e0);
            float4 aBh = *reinterpret_cast<const float4*>(al + hb * 128 + e0 + 4);
            float aAa[8] = {aAl.x, aAl.y, aAl.z, aAl.w, aAh.x, aAh.y, aAh.z, aAh.w};
            float aBa[8] = {aBl.x, aBl.y, aBl.z, aBl.w, aBh.x, aBh.y, aBh.z, aBh.w};
#pragma unroll
            for (int k = 0; k < 4; k++) {
                float4 s0l = *reinterpret_cast<const float4*>(shm + (2 * k) * 128 + e0);
                float4 s0h = *reinterpret_cast<const float4*>(shm + (2 * k) * 128 + e0 + 4);
                float4 s1l = *reinterpret_cast<const float4*>(shm + (2 * k + 1) * 128 + e0);
                float4 s1h = *reinterpret_cast<const float4*>(shm + (2 * k + 1) * 128 + e0 + 4);
                float s0a[8] = {s0l.x, s0l.y, s0l.z, s0l.w, s0h.x, s0h.y, s0h.z, s0h.w};
                float s1a[8] = {s1l.x, s1l.y, s1l.z, s1l.w, s1h.x, s1h.y, s1h.z, s1h.w};
                const bool b0 = (clo + 2 * k     >= thr);
                const bool b1 = (clo + 2 * k + 1 >= thr);
#pragma unroll
                for (int i = 0; i < 8; i++) {
                    float2 v = unpack2(acc[i][k]);
                    float a0 = b0 ? aBa[i] : aAa[i];
                    float a1 = b1 ? aBa[i] : aAa[i];
                    pk0[k] += xa[i] * s0a[i] * v.x * a0;
                    pk1[k] += xa[i] * s1a[i] * v.y * a1;
                }
            }
        }
        // reduce the two 8-edge halves of each node (lane bit 3)
#pragma unroll
        for (int k = 0; k < 4; k++) {
            pk0[k] += __shfl_xor_sync(0xffffffffu, pk0[k], 8);
            pk1[k] += __shfl_xor_sync(0xffffffffu, pk1[k], 8);
        }
        if ((tid & 8) == 0) {
            const int node = tid >> 4;
#pragma unroll
            for (int k = 0; k < 4; k++)
                *reinterpret_cast<float2*>(accN + node * FDIM + clo + 2 * k) =
                    make_float2(pk0[k], pk1[k]);
        }
    }
    __syncthreads();   // accN complete; act free for scratch

    // ---------- epilogue: out[n] = accN[n] @ W_out (576x64), c-split halves ----------
    {
        const int dcol = tid & 63;
        const int half = tid >> 6;
        const int cbeg = half * 288;
        float s[8] = {0.f, 0.f, 0.f, 0.f, 0.f, 0.f, 0.f, 0.f};
        for (int c = cbeg; c < cbeg + 288; c += 4) {
            float w0 = W_out[(c + 0) * 64 + dcol];
            float w1 = W_out[(c + 1) * 64 + dcol];
            float w2 = W_out[(c + 2) * 64 + dcol];
            float w3 = W_out[(c + 3) * 64 + dcol];
#pragma unroll
            for (int n = 0; n < 8; n++) {
                float4 a = *reinterpret_cast<const float4*>(accN + n * FDIM + c);
                s[n] += a.x * w0 + a.y * w1 + a.z * w2 + a.w * w3;
            }
        }
        float* scratch = act;
        if (half == 1) {
#pragma unroll
            for (int n = 0; n < 8; n++) scratch[n * 64 + dcol] = s[n];
        }
        __syncthreads();
        if (half == 0) {
#pragma unroll
            for (int n = 0; n < 8; n++)
                out[(n0 + n) * 64 + dcol] = s[n] + scratch[n * 64 + dcol];
        }
    }
#undef GEMM_INPLACE
}

extern "C" void kernel_launch(void* const* d_in, const int* in_sizes, int n_in,
                              void* d_out, int out_size) {
    const float* node_feat = (const float*)d_in[0];
    const float* edge_sh   = (const float*)d_in[1];
    const float* edge_inv  = (const float*)d_in[2];
    const float* cutoff    = (const float*)d_in[3];
    const float* Wk1       = (const float*)d_in[4];
    const float* Wk2       = (const float*)d_in[5];
    const float* Wk3       = (const float*)d_in[6];
    const float* Wv1       = (const float*)d_in[7];
    const float* Wv2       = (const float*)d_in[8];
    const float* Wv3       = (const float*)d_in[9];
    const float* W_logit   = (const float*)d_in[10];
    const float* W_out     = (const float*)d_in[11];
    const int*   edge_src  = (const int*)d_in[12];
    float* out = (float*)d_out;

    size_t smem = SMEM_FLOATS * sizeof(float);
    cudaFuncSetAttribute(fused_attn_kernel2,
                         cudaFuncAttributeMaxDynamicSharedMemorySize, (int)smem);
    fused_attn_kernel2<<<NNODES / GN, THREADS, smem>>>(
        node_feat, edge_sh, edge_inv, cutoff,
        Wk1, Wk2, Wk3, Wv1, Wv2, Wv3,
        W_logit, W_out, edge_src, out);
}

// round 7
// speedup vs baseline: 2.3675x; 2.3675x over previous
#include <cuda_runtime.h>
#include <math.h>

// Problem constants
#define KEDGE   16
#define SDIM    8
#define HHEAD   4
#define FDIM    576
#define FPH     144
#define NNODES  8192

// Tiling: 8 nodes (128 edges) per block, 4 warps, warp owns 32 edges (2 nodes)
#define GN      8
#define EPB     128
#define THREADS 128
#define ASTR    68          // act/xs row stride (floats): conflict-free frag loads

// smem layout (float offsets)
#define OFF_ACT 0                        // [128][68] activations (in-place chain)
#define OFF_XS  (OFF_ACT + EPB*ASTR)     // 8704   [128][68] x_src
#define OFF_QN  (OFF_XS + EPB*ASTR)      // 17408  [8][64]
#define OFF_SH  (OFF_QN + GN*64)         // 17920  [128][8]
#define OFF_WL  (OFF_SH + EPB*SDIM)      // 18944  [128][4]
#define OFF_LG  (OFF_WL + 512)           // 19456  [128][4]
#define OFF_AL  (OFF_LG + EPB*4)         // 19968  [128][4]
#define OFF_CW  (OFF_AL + EPB*4)         // 20480  [128]
#define OFF_ACC (OFF_CW + EPB)           // 20608  [8][576]
#define SMEM_FLOATS (OFF_ACC + GN*FDIM)  // 25216 floats = 100864 B -> 2 CTAs/SM

// ---- packed tf32 hi/lo weights (prep kernel output), float2 = (hi, lo) ----
#define PK_K1 0
#define PK_K2 4096
#define PK_K3 8192
#define PK_V1 45056
#define PK_V2 49152
#define PK_V3 53248
#define PK_TOTAL 90112
__device__ float2 g_Wpk[PK_TOTAL];

__device__ __forceinline__ void tf32_split(float v, unsigned &hi, unsigned &lo) {
    asm("cvt.rna.tf32.f32 %0, %1;" : "=r"(hi) : "f"(v));
    float lof = v - __uint_as_float(hi);
    asm("cvt.rna.tf32.f32 %0, %1;" : "=r"(lo) : "f"(lof));
}

__device__ __forceinline__ void mma8(float c[4], const unsigned a[4],
                                     unsigned b0, unsigned b1) {
    asm("mma.sync.aligned.m16n8k8.row.col.f32.tf32.tf32.f32 "
        "{%0,%1,%2,%3}, {%4,%5,%6,%7}, {%8,%9}, {%0,%1,%2,%3};"
        : "+f"(c[0]), "+f"(c[1]), "+f"(c[2]), "+f"(c[3])
        : "r"(a[0]), "r"(a[1]), "r"(a[2]), "r"(a[3]), "r"(b0), "r"(b1));
}

__device__ __forceinline__ float gelu_f(float x) {
    float u = 0.7978845608028654f * (x + 0.044715f * x * x * x);
    float t;
    asm("tanh.approx.f32 %0, %1;" : "=f"(t) : "f"(u));
    return 0.5f * x * (1.0f + t);
}

__global__ void prep_kernel(const float* __restrict__ Wk1, const float* __restrict__ Wk2,
                            const float* __restrict__ Wk3, const float* __restrict__ Wv1,
                            const float* __restrict__ Wv2, const float* __restrict__ Wv3) {
    int i = blockIdx.x * 256 + threadIdx.x;
    if (i >= PK_TOTAL) return;
    const float* src; int off;
    if      (i < PK_K2) { src = Wk1; off = i - PK_K1; }
    else if (i < PK_K3) { src = Wk2; off = i - PK_K2; }
    else if (i < PK_V1) { src = Wk3; off = i - PK_K3; }
    else if (i < PK_V2) { src = Wv1; off = i - PK_V1; }
    else if (i < PK_V3) { src = Wv2; off = i - PK_V2; }
    else                { src = Wv3; off = i - PK_V3; }
    float v = src[off];
    unsigned hi, lo;
    tf32_split(v, hi, lo);
    g_Wpk[i] = make_float2(__uint_as_float(hi), __uint_as_float(lo));
}

// Load + split A fragments for 2 m-atoms at K-block k0.
__device__ __forceinline__ void load_afrag(const float* __restrict__ act,
                                           int ew0, int gr, int tig, int k0,
                                           unsigned Ah[2][4], unsigned Al[2][4]) {
#pragma unroll
    for (int m = 0; m < 2; m++) {
        const float* ap = act + (ew0 + 16 * m + gr) * ASTR + k0 + tig;
        float a0 = ap[0];
        float a1 = ap[8 * ASTR];
        float a2 = ap[4];
        float a3 = ap[8 * ASTR + 4];
        tf32_split(a0, Ah[m][0], Al[m][0]);
        tf32_split(a1, Ah[m][1], Al[m][1]);
        tf32_split(a2, Ah[m][2], Al[m][2]);
        tf32_split(a3, Ah[m][3], Al[m][3]);
    }
}

// Full 64-col layer GEMM (in-place: reads+writes own 32 edge rows), gelu.
__device__ __forceinline__ void layer_gemm(float* __restrict__ act,
                                           const float2* __restrict__ Wp,
                                           int ew0, int gr, int tig) {
    float acc[2][8][4];
#pragma unroll
    for (int m = 0; m < 2; m++)
#pragma unroll
        for (int j = 0; j < 8; j++)
#pragma unroll
            for (int p = 0; p < 4; p++) acc[m][j][p] = 0.f;

#pragma unroll 2
    for (int k8 = 0; k8 < 8; k8++) {
        const int k0 = k8 * 8;
        unsigned Ah[2][4], Al[2][4];
        load_afrag(act, ew0, gr, tig, k0, Ah, Al);
        const float2* wr0 = Wp + (k0 + tig) * 64 + gr;
        const float2* wr1 = Wp + (k0 + tig + 4) * 64 + gr;
#pragma unroll
        for (int j = 0; j < 8; j++) {
            float2 b0p = wr0[j * 8];
            float2 b1p = wr1[j * 8];
            unsigned b0h = __float_as_uint(b0p.x), b0l = __float_as_uint(b0p.y);
            unsigned b1h = __float_as_uint(b1p.x), b1l = __float_as_uint(b1p.y);
#pragma unroll
            for (int m = 0; m < 2; m++) {
                mma8(acc[m][j], Ah[m], b0h, b1h);
                mma8(acc[m][j], Al[m], b0h, b1h);
                mma8(acc[m][j], Ah[m], b0l, b1l);
            }
        }
    }
    // gelu + in-place store (own rows only -> no barrier needed)
#pragma unroll
    for (int m = 0; m < 2; m++) {
        const int r0 = (ew0 + 16 * m + gr) * ASTR;
#pragma unroll
        for (int j = 0; j < 8; j++) {
            const int c = j * 8 + 2 * tig;
            *reinterpret_cast<float2*>(act + r0 + c) =
                make_float2(gelu_f(acc[m][j][0]), gelu_f(acc[m][j][1]));
            *reinterpret_cast<float2*>(act + r0 + 8 * ASTR + c) =
                make_float2(gelu_f(acc[m][j][2]), gelu_f(acc[m][j][3]));
        }
    }
}

// 32-col chunk-half GEMM into registers (layer-3, N-half of a 64-col chunk).
__device__ __forceinline__ void chunk_half(const float* __restrict__ act,
                                           const float2* __restrict__ Wp,
                                           int colbase, int ew0, int gr, int tig,
                                           float acc[2][4][4]) {
#pragma unroll
    for (int m = 0; m < 2; m++)
#pragma unroll
        for (int j = 0; j < 4; j++)
#pragma unroll
            for (int p = 0; p < 4; p++) acc[m][j][p] = 0.f;

#pragma unroll 2
    for (int k8 = 0; k8 < 8; k8++) {
        const int k0 = k8 * 8;
        unsigned Ah[2][4], Al[2][4];
        load_afrag(act, ew0, gr, tig, k0, Ah, Al);
        const float2* wr0 = Wp + (k0 + tig) * FDIM + colbase + gr;
        const float2* wr1 = Wp + (k0 + tig + 4) * FDIM + colbase + gr;
#pragma unroll
        for (int j = 0; j < 4; j++) {
            float2 b0p = wr0[j * 8];
            float2 b1p = wr1[j * 8];
            unsigned b0h = __float_as_uint(b0p.x), b0l = __float_as_uint(b0p.y);
            unsigned b1h = __float_as_uint(b1p.x), b1l = __float_as_uint(b1p.y);
#pragma unroll
            for (int m = 0; m < 2; m++) {
                mma8(acc[m][j], Ah[m], b0h, b1h);
                mma8(acc[m][j], Al[m], b0h, b1h);
                mma8(acc[m][j], Ah[m], b0l, b1l);
            }
        }
    }
}

__global__ __launch_bounds__(THREADS, 2)
void fused_attn_kernel(const float* __restrict__ node_feat,
                       const float* __restrict__ edge_sh,
                       const float* __restrict__ edge_inv,
                       const float* __restrict__ cutoff,
                       const float* __restrict__ W_logit,
                       const float* __restrict__ W_out,
                       const int* __restrict__ edge_src,
                       float* __restrict__ out) {
    extern __shared__ float sm[];
    const int tid  = threadIdx.x;
    const int warp = tid >> 5;
    const int lane = tid & 31;
    const int gr   = lane >> 2;     // 0..7  (fragment "groupID")
    const int tig  = lane & 3;      // 0..3  (thread-in-group)
    const int ew0  = warp * 32;     // warp's edge base (block-rel)
    const int n0   = blockIdx.x * GN;
    const int eg0  = blockIdx.x * EPB;

    float* act  = sm + OFF_ACT;
    float* xs   = sm + OFF_XS;
    float* qn   = sm + OFF_QN;
    float* shm  = sm + OFF_SH;
    float* WLs  = sm + OFF_WL;
    float* lg   = sm + OFF_LG;
    float* al   = sm + OFF_AL;
    float* cw   = sm + OFF_CW;
    float* accN = sm + OFF_ACC;

    // ---------- phase 0 ----------
    cw[tid] = cutoff[eg0 + tid];
    for (int i = tid; i < 512; i += THREADS) WLs[i] = W_logit[i];
    {   // q rows for this warp's 2 nodes (warp-local)
        int idx = lane * 4;
        *reinterpret_cast<float4*>(qn + warp * 128 + idx) =
            *reinterpret_cast<const float4*>(node_feat + (n0 + 2 * warp) * 64 + idx);
    }
    {   // sh, edge_inv, x_src for this warp's 32 edges (warp-local, lane = one edge)
        const int e = ew0 + lane;
        const int ge = eg0 + e;
        *reinterpret_cast<float4*>(shm + e * 8) =
            *reinterpret_cast<const float4*>(edge_sh + ge * 8);
        *reinterpret_cast<float4*>(shm + e * 8 + 4) =
            *reinterpret_cast<const float4*>(edge_sh + ge * 8 + 4);
        const int srce = edge_src[ge];
#pragma unroll
        for (int m4 = 0; m4 < 16; m4++) {
            *reinterpret_cast<float4*>(act + e * ASTR + m4 * 4) =
                *reinterpret_cast<const float4*>(edge_inv + ge * 64 + m4 * 4);
            *reinterpret_cast<float4*>(xs + e * ASTR + m4 * 4) =
                *reinterpret_cast<const float4*>(node_feat + srce * 64 + m4 * 4);
        }
    }
    __syncthreads();

    // hoist per-edge sh values at this thread's (2tig, 2tig+1) positions
    float shv0[4], shv1[4];
#pragma unroll
    for (int i = 0; i < 4; i++) {
        const int e = ew0 + 16 * (i >> 1) + 8 * (i & 1) + gr;
        shv0[i] = shm[e * 8 + 2 * tig];
        shv1[i] = shm[e * 8 + 2 * tig + 1];
    }

    // ---------- key MLP layers 1,2 (barrier-free, own rows) ----------
    layer_gemm(act, g_Wpk + PK_K1, ew0, gr, tig);
    layer_gemm(act, g_Wpk + PK_K2, ew0, gr, tig);

    // ---------- key layer-3 chunks -> logit partials ----------
    float pl[4][4];
#pragma unroll
    for (int i = 0; i < 4; i++)
#pragma unroll
        for (int h = 0; h < 4; h++) pl[i][h] = 0.f;

#pragma unroll 1
    for (int ci = 0; ci < 9; ci++) {
#pragma unroll 1
        for (int nh = 0; nh < 2; nh++) {
            float acc[2][4][4];
            chunk_half(act, g_Wpk + PK_K3, ci * 64 + nh * 32, ew0, gr, tig, acc);

            if (ci == 0) {
#pragma unroll
                for (int j = 0; j < 4; j++) {
                    const int t0 = nh * 32 + j * 8 + 2 * tig;
                    float4 wl0 = *reinterpret_cast<const float4*>(WLs + t0 * 4);
                    float4 wl1 = *reinterpret_cast<const float4*>(WLs + t0 * 4 + 4);
#pragma unroll
                    for (int m = 0; m < 2; m++) {
                        const float* qrow = qn + (2 * warp + m) * 64;
                        const float q0 = qrow[t0], q1 = qrow[t0 + 1];
                        const int eA = ew0 + 16 * m + gr, eB = eA + 8;
                        float cA0 = q0 * xs[eA * ASTR + t0]     * acc[m][j][0];
                        float cA1 = q1 * xs[eA * ASTR + t0 + 1] * acc[m][j][1];
                        float cB0 = q0 * xs[eB * ASTR + t0]     * acc[m][j][2];
                        float cB1 = q1 * xs[eB * ASTR + t0 + 1] * acc[m][j][3];
                        pl[2*m][0]   += cA0 * wl0.x + cA1 * wl1.x;
                        pl[2*m][1]   += cA0 * wl0.y + cA1 * wl1.y;
                        pl[2*m][2]   += cA0 * wl0.z + cA1 * wl1.z;
                        pl[2*m][3]   += cA0 * wl0.w + cA1 * wl1.w;
                        pl[2*m+1][0] += cB0 * wl0.x + cB1 * wl1.x;
                        pl[2*m+1][1] += cB0 * wl0.y + cB1 * wl1.y;
                        pl[2*m+1][2] += cB0 * wl0.z + cB1 * wl1.z;
                        pl[2*m+1][3] += cB0 * wl0.w + cB1 * wl1.w;
                    }
                }
            } else {
#pragma unroll
                for (int j = 0; j < 4; j++) {
                    const int dd = 8 * (ci - 1) + nh * 4 + j;
                    float4 wl = *reinterpret_cast<const float4*>(WLs + (64 + dd) * 4);
#pragma unroll
                    for (int m = 0; m < 2; m++) {
                        const float qd = qn[(2 * warp + m) * 64 + dd];
                        const int eA = ew0 + 16 * m + gr, eB = eA + 8;
                        const int iA = 2 * m, iB = 2 * m + 1;
                        float cA = qd * xs[eA * ASTR + dd] *
                                   (shv0[iA] * shv0[iA] * acc[m][j][0] +
                                    shv1[iA] * shv1[iA] * acc[m][j][1]);
                        float cB = qd * xs[eB * ASTR + dd] *
                                   (shv0[iB] * shv0[iB] * acc[m][j][2] +
                                    shv1[iB] * shv1[iB] * acc[m][j][3]);
                        pl[iA][0] += cA * wl.x; pl[iA][1] += cA * wl.y;
                        pl[iA][2] += cA * wl.z; pl[iA][3] += cA * wl.w;
                        pl[iB][0] += cB * wl.x; pl[iB][1] += cB * wl.y;
                        pl[iB][2] += cB * wl.z; pl[iB][3] += cB * wl.w;
                    }
                }
            }
        }
    }

    // reduce pl over the 4 tig lanes; lane tig==0 stores
#pragma unroll
    for (int msk = 1; msk < 4; msk <<= 1)
#pragma unroll
        for (int i = 0; i < 4; i++)
#pragma unroll
            for (int h = 0; h < 4; h++)
                pl[i][h] += __shfl_xor_sync(0xffffffffu, pl[i][h], msk);
    if (tig == 0) {
#pragma unroll
        for (int i = 0; i < 4; i++) {
            const int e = ew0 + 16 * (i >> 1) + 8 * (i & 1) + gr;
            *reinterpret_cast<float4*>(lg + e * 4) =
                make_float4(pl[i][0], pl[i][1], pl[i][2], pl[i][3]);
        }
    }

    // reload edge_inv into act (warp-local, own rows)
    {
        const int e = ew0 + lane;
#pragma unroll
        for (int m4 = 0; m4 < 16; m4++)
            *reinterpret_cast<float4*>(act + e * ASTR + m4 * 4) =
                *reinterpret_cast<const float4*>(edge_inv + (eg0 + e) * 64 + m4 * 4);
    }
    __syncthreads();   // lg visible

    // ---------- softmax (warp 0) ----------
    if (tid < GN * HHEAD) {
        int n = tid >> 2, h = tid & 3;
        float mx = -3.0e38f;
        for (int j = 0; j < KEDGE; j++)
            mx = fmaxf(mx, lg[(n * KEDGE + j) * 4 + h]);
        float z = 0.f;
        float ex[KEDGE];
        for (int j = 0; j < KEDGE; j++) {
            int e = n * KEDGE + j;
            ex[j] = cw[e] * expf(lg[e * 4 + h] - mx);
            z += ex[j];
        }
        if (z == 0.f) z = 1.f;
        float inv = 1.f / z;
        for (int j = 0; j < KEDGE; j++)
            al[(n * KEDGE + j) * 4 + h] = sqrtf(ex[j] * inv);
    }

    // ---------- value MLP layers 1,2 ----------
    layer_gemm(act, g_Wpk + PK_V1, ew0, gr, tig);
    layer_gemm(act, g_Wpk + PK_V2, ew0, gr, tig);
    __syncthreads();   // al visible before value folds

    // ---------- value layer-3 chunks -> node accumulators ----------
#pragma unroll 1
    for (int ci = 0; ci < 9; ci++) {
#pragma unroll 1
        for (int nh = 0; nh < 2; nh++) {
            float acc[2][4][4];
            chunk_half(act, g_Wpk + PK_V3, ci * 64 + nh * 32, ew0, gr, tig, acc);

            float pk[2][4][2];
            if (ci == 0) {
#pragma unroll
                for (int j = 0; j < 4; j++) {
                    const int t0 = nh * 32 + j * 8 + 2 * tig;
#pragma unroll
                    for (int m = 0; m < 2; m++) {
                        const int eA = ew0 + 16 * m + gr, eB = eA + 8;
                        const float aA = al[eA * 4], aB = al[eB * 4];
                        pk[m][j][0] = xs[eA * ASTR + t0]     * acc[m][j][0] * aA
                                    + xs[eB * ASTR + t0]     * acc[m][j][2] * aB;
                        pk[m][j][1] = xs[eA * ASTR + t0 + 1] * acc[m][j][1] * aA
                                    + xs[eB * ASTR + t0 + 1] * acc[m][j][3] * aB;
                    }
                }
            } else {
#pragma unroll
                for (int j = 0; j < 4; j++) {
                    const int dd = 8 * (ci - 1) + nh * 4 + j;
                    const int C0 = ci * 64 + nh * 32 + j * 8 + 2 * tig;
                    const int h0 = C0 / FPH, h1 = (C0 + 1) / FPH;
#pragma unroll
                    for (int m = 0; m < 2; m++) {
                        const int eA = ew0 + 16 * m + gr, eB = eA + 8;
                        const int iA = 2 * m, iB = 2 * m + 1;
                        const float xA = xs[eA * ASTR + dd], xB = xs[eB * ASTR + dd];
                        pk[m][j][0] = xA * shv0[iA] * acc[m][j][0] * al[eA * 4 + h0]
                                    + xB * shv0[iB] * acc[m][j][2] * al[eB * 4 + h0];
                        pk[m][j][1] = xA * shv1[iA] * acc[m][j][1] * al[eA * 4 + h1]
                                    + xB * shv1[iB] * acc[m][j][3] * al[eB * 4 + h1];
                    }
                }
            }
            // reduce over gr lanes (bits 2,3,4) -> per-node sums
#pragma unroll
            for (int m = 0; m < 2; m++)
#pragma unroll
                for (int j = 0; j < 4; j++)
#pragma unroll
                    for (int p = 0; p < 2; p++) {
                        pk[m][j][p] += __shfl_xor_sync(0xffffffffu, pk[m][j][p], 4);
                        pk[m][j][p] += __shfl_xor_sync(0xffffffffu, pk[m][j][p], 8);
                        pk[m][j][p] += __shfl_xor_sync(0xffffffffu, pk[m][j][p], 16);
                    }
            if (gr == 0) {
#pragma unroll
                for (int m = 0; m < 2; m++)
#pragma unroll
                    for (int j = 0; j < 4; j++)
                        *reinterpret_cast<float2*>(
                            accN + (2 * warp + m) * FDIM + ci * 64 + nh * 32 + j * 8 + 2 * tig) =
                            make_float2(pk[m][j][0], pk[m][j][1]);
            }
        }
    }
    __syncthreads();   // accN complete; act free as scratch

    // ---------- epilogue: out[n] = accN[n] @ W_out (576x64), c-split halves ----------
    {
        const int dcol = tid & 63;
        const int half = tid >> 6;
        const int cbeg = half * 288;
        float s[8] = {0.f, 0.f, 0.f, 0.f, 0.f, 0.f, 0.f, 0.f};
        for (int c = cbeg; c < cbeg + 288; c += 4) {
            float w0 = W_out[(c + 0) * 64 + dcol];
            float w1 = W_out[(c + 1) * 64 + dcol];
            float w2 = W_out[(c + 2) * 64 + dcol];
            float w3 = W_out[(c + 3) * 64 + dcol];
#pragma unroll
            for (int n = 0; n < 8; n++) {
                float4 a = *reinterpret_cast<const float4*>(accN + n * FDIM + c);
                s[n] += a.x * w0 + a.y * w1 + a.z * w2 + a.w * w3;
            }
        }
        float* scratch = act;
        if (half == 1) {
#pragma unroll
            for (int n = 0; n < 8; n++) scratch[n * 64 + dcol] = s[n];
        }
        __syncthreads();
        if (half == 0) {
#pragma unroll
            for (int n = 0; n < 8; n++)
                out[(n0 + n) * 64 + dcol] = s[n] + scratch[n * 64 + dcol];
        }
    }
}

extern "C" void kernel_launch(void* const* d_in, const int* in_sizes, int n_in,
                              void* d_out, int out_size) {
    const float* node_feat = (const float*)d_in[0];
    const float* edge_sh   = (const float*)d_in[1];
    const float* edge_inv  = (const float*)d_in[2];
    const float* cutoff    = (const float*)d_in[3];
    const float* Wk1       = (const float*)d_in[4];
    const float* Wk2       = (const float*)d_in[5];
    const float* Wk3       = (const float*)d_in[6];
    const float* Wv1       = (const float*)d_in[7];
    const float* Wv2       = (const float*)d_in[8];
    const float* Wv3       = (const float*)d_in[9];
    const float* W_logit   = (const float*)d_in[10];
    const float* W_out     = (const float*)d_in[11];
    const int*   edge_src  = (const int*)d_in[12];
    float* out = (float*)d_out;

    prep_kernel<<<(PK_TOTAL + 255) / 256, 256>>>(Wk1, Wk2, Wk3, Wv1, Wv2, Wv3);

    size_t smem = SMEM_FLOATS * sizeof(float);
    cudaFuncSetAttribute(fused_attn_kernel,
                         cudaFuncAttributeMaxDynamicSharedMemorySize, (int)smem);
    fused_attn_kernel<<<NNODES / GN, THREADS, smem>>>(
        node_feat, edge_sh, edge_inv, cutoff,
        W_logit, W_out, edge_src, out);
}

// round 8
// speedup vs baseline: 3.6154x; 1.5271x over previous
#include <cuda_runtime.h>
#include <math.h>

// Problem constants
#define KEDGE   16
#define SDIM    8
#define HHEAD   4
#define FDIM    576
#define FPH     144
#define NNODES  8192

// Tiling: 4 nodes (64 edges) per block, 4 warps, warp = 1 node = one m16 atom
#define GN      4
#define EPB     64
#define THREADS 128

#define HSTR    36    // act hi/lo row stride (u32): banks 4*gr+tig distinct
#define XSTR    68    // xs row stride (f32)

// smem offsets (4-byte units)
#define OFF_HI  0                       // [64][36] u32  (bf16x2 hi plane)
#define OFF_LO  (OFF_HI + EPB*HSTR)     // [64][36] u32  (bf16x2 lo plane)
#define OFF_XS  (OFF_LO + EPB*HSTR)     // [64][68] f32
#define OFF_QN  (OFF_XS + EPB*XSTR)     // [4][64]
#define OFF_SH  (OFF_QN + GN*64)        // [64][8]
#define OFF_WL  (OFF_SH + EPB*SDIM)     // [128][4]
#define OFF_LG  (OFF_WL + 512)          // [64][4]
#define OFF_AL  (OFF_LG + EPB*4)        // [64][4]
#define OFF_CW  (OFF_AL + EPB*4)        // [64]
#define OFF_ACC (OFF_CW + EPB)          // [4][576]
#define SMEM_U32 (OFF_ACC + GN*FDIM)    // 13120 u32 = 52480 B -> 3 CTAs/SM

// ---- packed bf16x2 weights (prep output): hi plane then lo plane per matrix ----
// u32 index = k2*ncols + n ; element packs W[2*k2][n] (lo16) and W[2*k2+1][n] (hi16)
#define PK_K1 0        // 64x64: hi 2048, lo 2048
#define PK_K2 4096
#define PK_V1 8192
#define PK_V2 12288
#define PK_K3 16384    // 64x576: hi 18432, lo 18432
#define PK_V3 53248
#define PK_U32 90112
#define L_OFF_SMALL 2048
#define L_OFF_BIG   18432
__device__ unsigned g_Wpk[PK_U32];

__device__ __forceinline__ unsigned pack_bf16x2(float v_odd, float v_even) {
    unsigned r;
    asm("cvt.rn.bf16x2.f32 %0, %1, %2;" : "=r"(r) : "f"(v_odd), "f"(v_even));
    return r;
}
__device__ __forceinline__ float bf_lo_f(unsigned u) { return __uint_as_float(u << 16); }
__device__ __forceinline__ float bf_hi_f(unsigned u) { return __uint_as_float(u & 0xffff0000u); }

__device__ __forceinline__ void mma16(float c[4], const unsigned a[4],
                                      unsigned b0, unsigned b1) {
    asm("mma.sync.aligned.m16n8k16.row.col.f32.bf16.bf16.f32 "
        "{%0,%1,%2,%3}, {%4,%5,%6,%7}, {%8,%9}, {%0,%1,%2,%3};"
        : "+f"(c[0]), "+f"(c[1]), "+f"(c[2]), "+f"(c[3])
        : "r"(a[0]), "r"(a[1]), "r"(a[2]), "r"(a[3]), "r"(b0), "r"(b1));
}

__device__ __forceinline__ float gelu_f(float x) {
    float u = 0.7978845608028654f * (x + 0.044715f * x * x * x);
    float t;
    asm("tanh.approx.f32 %0, %1;" : "=f"(t) : "f"(u));
    return 0.5f * x * (1.0f + t);
}

__global__ void prep_kernel(const float* __restrict__ Wk1, const float* __restrict__ Wk2,
                            const float* __restrict__ Wk3, const float* __restrict__ Wv1,
                            const float* __restrict__ Wv2, const float* __restrict__ Wv3) {
    int p = blockIdx.x * 256 + threadIdx.x;
    if (p >= 45056) return;
    const float* src; int ncols, npairs, base, q;
    if      (p < 2048)  { src = Wk1; ncols = 64;  npairs = 2048;  base = PK_K1; q = p; }
    else if (p < 4096)  { src = Wk2; ncols = 64;  npairs = 2048;  base = PK_K2; q = p - 2048; }
    else if (p < 6144)  { src = Wv1; ncols = 64;  npairs = 2048;  base = PK_V1; q = p - 4096; }
    else if (p < 8192)  { src = Wv2; ncols = 64;  npairs = 2048;  base = PK_V2; q = p - 6144; }
    else if (p < 26624) { src = Wk3; ncols = 576; npairs = 18432; base = PK_K3; q = p - 8192; }
    else                { src = Wv3; ncols = 576; npairs = 18432; base = PK_V3; q = p - 26624; }
    int k2 = q / ncols, n = q % ncols;
    float v0 = src[(2 * k2) * ncols + n];
    float v1 = src[(2 * k2 + 1) * ncols + n];
    unsigned h = pack_bf16x2(v1, v0);
    float r0 = v0 - bf_lo_f(h);
    float r1 = v1 - bf_hi_f(h);
    unsigned l = pack_bf16x2(r1, r0);
    g_Wpk[base + q] = h;
    g_Wpk[base + npairs + q] = l;
}

// 16x64x64 GEMM for one warp's node: in-place gelu+split store into hi/lo planes.
__device__ __forceinline__ void layer_gemm(unsigned* hi, unsigned* lo,
                                           const unsigned* __restrict__ Wb,
                                           int ew0, int gr, int tig) {
    float acc[8][4];
#pragma unroll
    for (int j = 0; j < 8; j++)
#pragma unroll
        for (int p = 0; p < 4; p++) acc[j][p] = 0.f;

    const unsigned* Wl = Wb + L_OFF_SMALL;
    const int rA = (ew0 + gr) * HSTR;
    const int rB = (ew0 + gr + 8) * HSTR;
#pragma unroll
    for (int kb = 0; kb < 4; kb++) {
        const int k2 = kb * 8;
        unsigned Ah[4] = { hi[rA + k2 + tig], hi[rB + k2 + tig],
                           hi[rA + k2 + tig + 4], hi[rB + k2 + tig + 4] };
        unsigned Al[4] = { lo[rA + k2 + tig], lo[rB + k2 + tig],
                           lo[rA + k2 + tig + 4], lo[rB + k2 + tig + 4] };
        const unsigned* w0h = Wb + (k2 + tig) * 64 + gr;
        const unsigned* w1h = Wb + (k2 + tig + 4) * 64 + gr;
        const unsigned* w0l = Wl + (k2 + tig) * 64 + gr;
        const unsigned* w1l = Wl + (k2 + tig + 4) * 64 + gr;
#pragma unroll
        for (int j = 0; j < 8; j++) {
            unsigned b0 = w0h[j * 8], b1 = w1h[j * 8];
            unsigned c0 = w0l[j * 8], c1 = w1l[j * 8];
            mma16(acc[j], Ah, b0, b1);
            mma16(acc[j], Al, b0, b1);
            mma16(acc[j], Ah, c0, c1);
        }
    }
    // gelu + split + store (warp lockstep: all loads above precede stores)
#pragma unroll
    for (int j = 0; j < 8; j++) {
        float g0 = gelu_f(acc[j][0]), g1 = gelu_f(acc[j][1]);
        float g2 = gelu_f(acc[j][2]), g3 = gelu_f(acc[j][3]);
        unsigned hA = pack_bf16x2(g1, g0);
        unsigned hB = pack_bf16x2(g3, g2);
        unsigned lA = pack_bf16x2(g1 - bf_hi_f(hA), g0 - bf_lo_f(hA));
        unsigned lB = pack_bf16x2(g3 - bf_hi_f(hB), g2 - bf_lo_f(hB));
        const int cc = 4 * j + tig;
        hi[rA + cc] = hA; hi[rB + cc] = hB;
        lo[rA + cc] = lA; lo[rB + cc] = lB;
    }
    __syncwarp();
}

// 16x64 chunk of layer-3: acc left in registers for the fold.
__device__ __forceinline__ void chunk_gemm(const unsigned* hi, const unsigned* lo,
                                           const unsigned* __restrict__ Wb, int colb,
                                           int ew0, int gr, int tig, float acc[8][4]) {
#pragma unroll
    for (int j = 0; j < 8; j++)
#pragma unroll
        for (int p = 0; p < 4; p++) acc[j][p] = 0.f;

    const unsigned* Wl = Wb + L_OFF_BIG;
    const int rA = (ew0 + gr) * HSTR;
    const int rB = (ew0 + gr + 8) * HSTR;
#pragma unroll
    for (int kb = 0; kb < 4; kb++) {
        const int k2 = kb * 8;
        unsigned Ah[4] = { hi[rA + k2 + tig], hi[rB + k2 + tig],
                           hi[rA + k2 + tig + 4], hi[rB + k2 + tig + 4] };
        unsigned Al[4] = { lo[rA + k2 + tig], lo[rB + k2 + tig],
                           lo[rA + k2 + tig + 4], lo[rB + k2 + tig + 4] };
        const unsigned* w0h = Wb + (k2 + tig) * FDIM + colb + gr;
        const unsigned* w1h = Wb + (k2 + tig + 4) * FDIM + colb + gr;
        const unsigned* w0l = Wl + (k2 + tig) * FDIM + colb + gr;
        const unsigned* w1l = Wl + (k2 + tig + 4) * FDIM + colb + gr;
#pragma unroll
        for (int j = 0; j < 8; j++) {
            unsigned b0 = w0h[j * 8], b1 = w1h[j * 8];
            unsigned c0 = w0l[j * 8], c1 = w1l[j * 8];
            mma16(acc[j], Ah, b0, b1);
            mma16(acc[j], Al, b0, b1);
            mma16(acc[j], Ah, c0, c1);
        }
    }
}

// split a float4 of f32 into hi/lo bf16x2 pairs and store
__device__ __forceinline__ void split_store4(unsigned* hi, unsigned* lo, int idx, float4 v) {
    unsigned h0 = pack_bf16x2(v.y, v.x);
    unsigned h1 = pack_bf16x2(v.w, v.z);
    unsigned l0 = pack_bf16x2(v.y - bf_hi_f(h0), v.x - bf_lo_f(h0));
    unsigned l1 = pack_bf16x2(v.w - bf_hi_f(h1), v.z - bf_lo_f(h1));
    hi[idx] = h0; hi[idx + 1] = h1;
    lo[idx] = l0; lo[idx + 1] = l1;
}

__global__ __launch_bounds__(THREADS, 3)
void fused_attn_kernel(const float* __restrict__ node_feat,
                       const float* __restrict__ edge_sh,
                       const float* __restrict__ edge_inv,
                       const float* __restrict__ cutoff,
                       const float* __restrict__ W_logit,
                       const float* __restrict__ W_out,
                       const int* __restrict__ edge_src,
                       float* __restrict__ out) {
    extern __shared__ unsigned smu[];
    unsigned* hi  = smu + OFF_HI;
    unsigned* lo  = smu + OFF_LO;
    float* xs   = (float*)(smu + OFF_XS);
    float* qn   = (float*)(smu + OFF_QN);
    float* shm  = (float*)(smu + OFF_SH);
    float* WLs  = (float*)(smu + OFF_WL);
    float* lg   = (float*)(smu + OFF_LG);
    float* al   = (float*)(smu + OFF_AL);
    float* cw   = (float*)(smu + OFF_CW);
    float* accN = (float*)(smu + OFF_ACC);

    const int tid  = threadIdx.x;
    const int warp = tid >> 5;
    const int lane = tid & 31;
    const int gr   = lane >> 2;
    const int tig  = lane & 3;
    const int ew0  = warp * 16;           // warp owns edges [ew0, ew0+16)
    const int n0   = blockIdx.x * GN;
    const int eg0  = blockIdx.x * EPB;

    // ---------- phase 0 ----------
    if (tid < EPB) cw[tid] = cutoff[eg0 + tid];
    for (int i = tid; i < 512; i += THREADS) WLs[i] = W_logit[i];
    {   // q row for this warp's node
        const int i2 = lane * 2;
        *reinterpret_cast<float2*>(qn + warp * 64 + i2) =
            *reinterpret_cast<const float2*>(node_feat + (n0 + warp) * 64 + i2);
    }
    {   // per-edge: 2 lanes per edge, each half the columns
        const int e    = ew0 + (lane >> 1);
        const int half = lane & 1;
        const int ge   = eg0 + e;
        *reinterpret_cast<float4*>(shm + e * 8 + half * 4) =
            *reinterpret_cast<const float4*>(edge_sh + ge * 8 + half * 4);
        const int srce = edge_src[ge];
#pragma unroll
        for (int m = 0; m < 8; m++) {
            const int c4 = half * 32 + m * 4;
            float4 v = *reinterpret_cast<const float4*>(edge_inv + ge * 64 + c4);
            split_store4(hi, lo, e * HSTR + c4 / 2, v);
            *reinterpret_cast<float4*>(xs + e * XSTR + c4) =
                *reinterpret_cast<const float4*>(node_feat + srce * 64 + c4);
        }
    }
    __syncthreads();

    // hoisted per-edge sh values at this thread's two columns
    const int eA = ew0 + gr, eB = ew0 + gr + 8;
    const float shvA0 = shm[eA * 8 + 2 * tig], shvA1 = shm[eA * 8 + 2 * tig + 1];
    const float shvB0 = shm[eB * 8 + 2 * tig], shvB1 = shm[eB * 8 + 2 * tig + 1];

    // ---------- key MLP layers 1,2 ----------
    layer_gemm(hi, lo, g_Wpk + PK_K1, ew0, gr, tig);
    layer_gemm(hi, lo, g_Wpk + PK_K2, ew0, gr, tig);

    // ---------- key layer-3 chunks -> logit partials ----------
    float pl[2][4];
#pragma unroll
    for (int i = 0; i < 2; i++)
#pragma unroll
        for (int h = 0; h < 4; h++) pl[i][h] = 0.f;

    const float* qrow = qn + warp * 64;

#pragma unroll 1
    for (int ci = 0; ci < 9; ci++) {
        float acc[8][4];
        chunk_gemm(hi, lo, g_Wpk + PK_K3, ci * 64, ew0, gr, tig, acc);

        if (ci == 0) {
#pragma unroll
            for (int j = 0; j < 8; j++) {
                const int t0 = 8 * j + 2 * tig;
                float4 wl0 = *reinterpret_cast<const float4*>(WLs + t0 * 4);
                float4 wl1 = *reinterpret_cast<const float4*>(WLs + t0 * 4 + 4);
                const float q0 = qrow[t0], q1 = qrow[t0 + 1];
                float cA0 = q0 * xs[eA * XSTR + t0]     * acc[j][0];
                float cA1 = q1 * xs[eA * XSTR + t0 + 1] * acc[j][1];
                float cB0 = q0 * xs[eB * XSTR + t0]     * acc[j][2];
                float cB1 = q1 * xs[eB * XSTR + t0 + 1] * acc[j][3];
                pl[0][0] += cA0 * wl0.x + cA1 * wl1.x;
                pl[0][1] += cA0 * wl0.y + cA1 * wl1.y;
                pl[0][2] += cA0 * wl0.z + cA1 * wl1.z;
                pl[0][3] += cA0 * wl0.w + cA1 * wl1.w;
                pl[1][0] += cB0 * wl0.x + cB1 * wl1.x;
                pl[1][1] += cB0 * wl0.y + cB1 * wl1.y;
                pl[1][2] += cB0 * wl0.z + cB1 * wl1.z;
                pl[1][3] += cB0 * wl0.w + cB1 * wl1.w;
            }
        } else {
#pragma unroll
            for (int j = 0; j < 8; j++) {
                const int d = 8 * (ci - 1) + j;
                float4 wl = *reinterpret_cast<const float4*>(WLs + (64 + d) * 4);
                const float qd = qrow[d];
                float cA = qd * xs[eA * XSTR + d] *
                           (shvA0 * shvA0 * acc[j][0] + shvA1 * shvA1 * acc[j][1]);
                float cB = qd * xs[eB * XSTR + d] *
                           (shvB0 * shvB0 * acc[j][2] + shvB1 * shvB1 * acc[j][3]);
                pl[0][0] += cA * wl.x; pl[0][1] += cA * wl.y;
                pl[0][2] += cA * wl.z; pl[0][3] += cA * wl.w;
                pl[1][0] += cB * wl.x; pl[1][1] += cB * wl.y;
                pl[1][2] += cB * wl.z; pl[1][3] += cB * wl.w;
            }
        }
    }

    // reduce pl over the 4 tig lanes; tig==0 stores
#pragma unroll
    for (int msk = 1; msk < 4; msk <<= 1)
#pragma unroll
        for (int i = 0; i < 2; i++)
#pragma unroll
            for (int h = 0; h < 4; h++)
                pl[i][h] += __shfl_xor_sync(0xffffffffu, pl[i][h], msk);
    if (tig == 0) {
        *reinterpret_cast<float4*>(lg + eA * 4) =
            make_float4(pl[0][0], pl[0][1], pl[0][2], pl[0][3]);
        *reinterpret_cast<float4*>(lg + eB * 4) =
            make_float4(pl[1][0], pl[1][1], pl[1][2], pl[1][3]);
    }
    __syncwarp();

    // reload edge_inv split (warp-local rows)
    {
        const int e    = ew0 + (lane >> 1);
        const int half = lane & 1;
        const int ge   = eg0 + e;
#pragma unroll
        for (int m = 0; m < 8; m++) {
            const int c4 = half * 32 + m * 4;
            float4 v = *reinterpret_cast<const float4*>(edge_inv + ge * 64 + c4);
            split_store4(hi, lo, e * HSTR + c4 / 2, v);
        }
    }
    __syncthreads();   // lg visible to warp 0

    // ---------- softmax ----------
    if (tid < GN * HHEAD) {
        const int n = tid >> 2, h = tid & 3;
        float mx = -3.0e38f;
        for (int j = 0; j < KEDGE; j++)
            mx = fmaxf(mx, lg[(n * KEDGE + j) * 4 + h]);
        float z = 0.f;
        float ex[KEDGE];
        for (int j = 0; j < KEDGE; j++) {
            const int e = n * KEDGE + j;
            ex[j] = cw[e] * expf(lg[e * 4 + h] - mx);
            z += ex[j];
        }
        if (z == 0.f) z = 1.f;
        const float inv = 1.f / z;
        for (int j = 0; j < KEDGE; j++)
            al[(n * KEDGE + j) * 4 + h] = sqrtf(ex[j] * inv);
    }

    // ---------- value MLP layers 1,2 (independent of al) ----------
    layer_gemm(hi, lo, g_Wpk + PK_V1, ew0, gr, tig);
    layer_gemm(hi, lo, g_Wpk + PK_V2, ew0, gr, tig);
    __syncthreads();   // al visible

    // ---------- value layer-3 chunks -> node accumulators ----------
#pragma unroll 1
    for (int ci = 0; ci < 9; ci++) {
        float acc[8][4];
        chunk_gemm(hi, lo, g_Wpk + PK_V3, ci * 64, ew0, gr, tig, acc);

        float pk[8][2];
        if (ci == 0) {
            const float aA = al[eA * 4], aB = al[eB * 4];
#pragma unroll
            for (int j = 0; j < 8; j++) {
                const int t0 = 8 * j + 2 * tig;
                pk[j][0] = xs[eA * XSTR + t0]     * acc[j][0] * aA
                         + xs[eB * XSTR + t0]     * acc[j][2] * aB;
                pk[j][1] = xs[eA * XSTR + t0 + 1] * acc[j][1] * aA
                         + xs[eB * XSTR + t0 + 1] * acc[j][3] * aB;
            }
        } else {
#pragma unroll
            for (int j = 0; j < 8; j++) {
                const int d  = 8 * (ci - 1) + j;
                const int C0 = ci * 64 + 8 * j + 2 * tig;
                const int h0 = C0 / FPH, h1 = (C0 + 1) / FPH;
                const float xA = xs[eA * XSTR + d], xB = xs[eB * XSTR + d];
                pk[j][0] = xA * shvA0 * acc[j][0] * al[eA * 4 + h0]
                         + xB * shvB0 * acc[j][2] * al[eB * 4 + h0];
                pk[j][1] = xA * shvA1 * acc[j][1] * al[eA * 4 + h1]
                         + xB * shvB1 * acc[j][3] * al[eB * 4 + h1];
            }
        }
        // reduce over gr lanes -> node sum over 16 edges
#pragma unroll
        for (int j = 0; j < 8; j++)
#pragma unroll
            for (int p = 0; p < 2; p++) {
                pk[j][p] += __shfl_xor_sync(0xffffffffu, pk[j][p], 4);
                pk[j][p] += __shfl_xor_sync(0xffffffffu, pk[j][p], 8);
                pk[j][p] += __shfl_xor_sync(0xffffffffu, pk[j][p], 16);
            }
        if (gr == 0) {
#pragma unroll
            for (int j = 0; j < 8; j++)
                *reinterpret_cast<float2*>(accN + warp * FDIM + ci * 64 + 8 * j + 2 * tig) =
                    make_float2(pk[j][0], pk[j][1]);
        }
    }
    __syncthreads();   // accN complete; hi/lo free as scratch

    // ---------- epilogue: out[n] = accN[n] @ W_out (576x64), c-split halves ----------
    {
        const int dcol = tid & 63;
        const int half = tid >> 6;
        const int cbeg = half * 288;
        float s[4] = {0.f, 0.f, 0.f, 0.f};
        for (int c = cbeg; c < cbeg + 288; c += 4) {
            float w0 = W_out[(c + 0) * 64 + dcol];
            float w1 = W_out[(c + 1) * 64 + dcol];
            float w2 = W_out[(c + 2) * 64 + dcol];
            float w3 = W_out[(c + 3) * 64 + dcol];
#pragma unroll
            for (int n = 0; n < 4; n++) {
                float4 a = *reinterpret_cast<const float4*>(accN + n * FDIM + c);
                s[n] += a.x * w0 + a.y * w1 + a.z * w2 + a.w * w3;
            }
        }
        float* scratch = (float*)(smu + OFF_HI);
        if (half == 1) {
#pragma unroll
            for (int n = 0; n < 4; n++) scratch[n * 64 + dcol] = s[n];
        }
        __syncthreads();
        if (half == 0) {
#pragma unroll
            for (int n = 0; n < 4; n++)
                out[(n0 + n) * 64 + dcol] = s[n] + scratch[n * 64 + dcol];
        }
    }
}

extern "C" void kernel_launch(void* const* d_in, const int* in_sizes, int n_in,
                              void* d_out, int out_size) {
    const float* node_feat = (const float*)d_in[0];
    const float* edge_sh   = (const float*)d_in[1];
    const float* edge_inv  = (const float*)d_in[2];
    const float* cutoff    = (const float*)d_in[3];
    const float* Wk1       = (const float*)d_in[4];
    const float* Wk2       = (const float*)d_in[5];
    const float* Wk3       = (const float*)d_in[6];
    const float* Wv1       = (const float*)d_in[7];
    const float* Wv2       = (const float*)d_in[8];
    const float* Wv3       = (const float*)d_in[9];
    const float* W_logit   = (const float*)d_in[10];
    const float* W_out     = (const float*)d_in[11];
    const int*   edge_src  = (const int*)d_in[12];
    float* out = (float*)d_out;

    prep_kernel<<<176, 256>>>(Wk1, Wk2, Wk3, Wv1, Wv2, Wv3);

    size_t smem = SMEM_U32 * 4;
    cudaFuncSetAttribute(fused_attn_kernel,
                         cudaFuncAttributeMaxDynamicSharedMemorySize, (int)smem);
    fused_attn_kernel<<<NNODES / GN, THREADS, smem>>>(
        node_feat, edge_sh, edge_inv, cutoff,
        W_logit, W_out, edge_src, out);
}

// round 9
// speedup vs baseline: 6.0231x; 1.6660x over previous
#include <cuda_runtime.h>
#include <math.h>

// Problem constants
#define KEDGE   16
#define SDIM    8
#define HHEAD   4
#define FDIM    576
#define FPH     144
#define NNODES  8192

// Tiling: 4 nodes (64 edges) per block, 4 warps, warp = 1 node = one m16 atom
#define GN      4
#define EPB     64
#define THREADS 128
#define XSTR    68    // xs row stride (f32)

// smem offsets (u32 units)
// act: per-warp fragment-quad region: warp w -> u32 [w*1024, w*1024+1024)
//   hi quads: words [0,512), lo quads: words [512,1024)
//   quad(c2, gr) = ((c2>>3)*4 + (c2&3))*8 + gr ; word = quad*4 + ((c2>>2)&1)*2 + gr8
#define OFF_ACT 0                       // 4096 u32 (16 KB)
#define OFF_XS  4096                    // [64][68] f32 = 4352
#define OFF_QN  (OFF_XS + EPB*XSTR)     // [4][64]
#define OFF_SH  (OFF_QN + GN*64)        // [64][8]
#define OFF_WL  (OFF_SH + EPB*SDIM)     // [128][4]
#define OFF_LG  (OFF_WL + 512)          // [64][4]
#define OFF_AL  (OFF_LG + EPB*4)        // [64][4]
#define OFF_CW  (OFF_AL + EPB*4)        // [64]
#define OFF_ACC (OFF_CW + EPB)          // [4][576]
#define SMEM_U32 (OFF_ACC + GN*FDIM)    // 12608 u32 = 50432 B -> 3 CTAs/SM

// ---- fragment-ordered packed weights: uint4 {b0h, b1h, b0l, b1l} ----
// uint4 index within a matrix: (jblk*4 + kb)*32 + lane
//   b0 = bf16x2 of source rows 2*(kb*8+tig), 2*(kb*8+tig)+1  at col jblk*8+gr
//   b1 = same for rows 2*(kb*8+tig+4), +1
#define Q_K1 0          // 64x64 -> 1024 uint4
#define Q_K2 1024
#define Q_V1 2048
#define Q_V2 3072
#define Q_K3 4096       // 64x576 -> 9216 uint4
#define Q_V3 13312
#define Q_TOTAL 22528
__device__ uint4 g_Wpk[Q_TOTAL];

__device__ __forceinline__ unsigned pack_bf16x2(float v_odd, float v_even) {
    unsigned r;
    asm("cvt.rn.bf16x2.f32 %0, %1, %2;" : "=r"(r) : "f"(v_odd), "f"(v_even));
    return r;
}
__device__ __forceinline__ float bf_lo_f(unsigned u) { return __uint_as_float(u << 16); }
__device__ __forceinline__ float bf_hi_f(unsigned u) { return __uint_as_float(u & 0xffff0000u); }

__device__ __forceinline__ void mma16(float c[4], const unsigned a[4],
                                      unsigned b0, unsigned b1) {
    asm("mma.sync.aligned.m16n8k16.row.col.f32.bf16.bf16.f32 "
        "{%0,%1,%2,%3}, {%4,%5,%6,%7}, {%8,%9}, {%0,%1,%2,%3};"
        : "+f"(c[0]), "+f"(c[1]), "+f"(c[2]), "+f"(c[3])
        : "r"(a[0]), "r"(a[1]), "r"(a[2]), "r"(a[3]), "r"(b0), "r"(b1));
}

__device__ __forceinline__ float gelu_f(float x) {
    float u = 0.7978845608028654f * (x + 0.044715f * x * x * x);
    float t;
    asm("tanh.approx.f32 %0, %1;" : "=f"(t) : "f"(u));
    return 0.5f * x * (1.0f + t);
}

__global__ void prep_kernel(const float* __restrict__ Wk1, const float* __restrict__ Wk2,
                            const float* __restrict__ Wk3, const float* __restrict__ Wv1,
                            const float* __restrict__ Wv2, const float* __restrict__ Wv3) {
    int i = blockIdx.x * 256 + threadIdx.x;
    if (i >= Q_TOTAL) return;
    const float* src; int ncols, q;
    if      (i < Q_K2) { src = Wk1; ncols = 64;  q = i - Q_K1; }
    else if (i < Q_V1) { src = Wk2; ncols = 64;  q = i - Q_K2; }
    else if (i < Q_V2) { src = Wv1; ncols = 64;  q = i - Q_V1; }
    else if (i < Q_K3) { src = Wv2; ncols = 64;  q = i - Q_V2; }
    else if (i < Q_V3) { src = Wk3; ncols = 576; q = i - Q_K3; }
    else               { src = Wv3; ncols = 576; q = i - Q_V3; }
    const int jblk = q >> 7;
    const int kb   = (q >> 5) & 3;
    const int lane = q & 31;
    const int gr   = lane >> 2;
    const int tig  = lane & 3;
    const int n    = jblk * 8 + gr;
    const int kA   = 2 * (kb * 8 + tig);
    const int kB   = 2 * (kb * 8 + tig + 4);
    float a0 = src[kA * ncols + n],       a1 = src[(kA + 1) * ncols + n];
    float b0 = src[kB * ncols + n],       b1 = src[(kB + 1) * ncols + n];
    unsigned h0 = pack_bf16x2(a1, a0);
    unsigned h1 = pack_bf16x2(b1, b0);
    unsigned l0 = pack_bf16x2(a1 - bf_hi_f(h0), a0 - bf_lo_f(h0));
    unsigned l1 = pack_bf16x2(b1 - bf_hi_f(h1), b0 - bf_lo_f(h1));
    uint4 o; o.x = h0; o.y = h1; o.z = l0; o.w = l1;
    g_Wpk[i] = o;
}

// write one (c2) column-pair for this edge into the fragment-quad act layout
__device__ __forceinline__ void act_store_c2(unsigned* hw, unsigned* lw,
                                             int c2, int gr_e, int gr8,
                                             float v0, float v1) {
    unsigned h = pack_bf16x2(v1, v0);
    unsigned l = pack_bf16x2(v1 - bf_hi_f(h), v0 - bf_lo_f(h));
    const int quad = ((c2 >> 3) * 4 + (c2 & 3)) * 8 + gr_e;
    const int idx  = quad * 4 + ((c2 >> 2) & 1) * 2 + gr8;
    hw[idx] = h;
    lw[idx] = l;
}

// 16x64x64 layer GEMM, in-place gelu+split store. actq = warp's uint4 base.
__device__ __forceinline__ void layer_gemm(uint4* actq, const uint4* __restrict__ Wq,
                                           int gr, int tig, int lane) {
    float acc[8][4];
#pragma unroll
    for (int j = 0; j < 8; j++)
#pragma unroll
        for (int p = 0; p < 4; p++) acc[j][p] = 0.f;

#pragma unroll
    for (int kb = 0; kb < 4; kb++) {
        uint4 ahq = actq[(kb * 4 + tig) * 8 + gr];
        uint4 alq = actq[128 + (kb * 4 + tig) * 8 + gr];
        unsigned Ah[4] = {ahq.x, ahq.y, ahq.z, ahq.w};
        unsigned Al[4] = {alq.x, alq.y, alq.z, alq.w};
        const uint4* wp = Wq + kb * 32 + lane;
#pragma unroll
        for (int j = 0; j < 8; j++) {
            uint4 w = wp[j * 128];
            mma16(acc[j], Ah, w.x, w.y);
            mma16(acc[j], Al, w.x, w.y);
            mma16(acc[j], Ah, w.z, w.w);
        }
    }
    __syncwarp();
    unsigned* hw = (unsigned*)actq;
    unsigned* lw = hw + 512;
#pragma unroll
    for (int j = 0; j < 8; j++) {
        float g0 = gelu_f(acc[j][0]), g1 = gelu_f(acc[j][1]);
        float g2 = gelu_f(acc[j][2]), g3 = gelu_f(acc[j][3]);
        unsigned hA = pack_bf16x2(g1, g0);
        unsigned hB = pack_bf16x2(g3, g2);
        unsigned lA = pack_bf16x2(g1 - bf_hi_f(hA), g0 - bf_lo_f(hA));
        unsigned lB = pack_bf16x2(g3 - bf_hi_f(hB), g2 - bf_lo_f(hB));
        const int c2   = j * 4 + tig;
        const int quad = ((c2 >> 3) * 4 + (c2 & 3)) * 8 + gr;
        const int base = quad * 4 + ((c2 >> 2) & 1) * 2;
        *reinterpret_cast<uint2*>(hw + base) = make_uint2(hA, hB);
        *reinterpret_cast<uint2*>(lw + base) = make_uint2(lA, lB);
    }
    __syncwarp();
}

// 16x64 chunk of a 64x576 layer-3 GEMM; acc left in registers.
__device__ __forceinline__ void chunk_gemm(const uint4* actq, const uint4* __restrict__ Wq,
                                           int ci, int gr, int tig, int lane,
                                           float acc[8][4]) {
#pragma unroll
    for (int j = 0; j < 8; j++)
#pragma unroll
        for (int p = 0; p < 4; p++) acc[j][p] = 0.f;

#pragma unroll
    for (int kb = 0; kb < 4; kb++) {
        uint4 ahq = actq[(kb * 4 + tig) * 8 + gr];
        uint4 alq = actq[128 + (kb * 4 + tig) * 8 + gr];
        unsigned Ah[4] = {ahq.x, ahq.y, ahq.z, ahq.w};
        unsigned Al[4] = {alq.x, alq.y, alq.z, alq.w};
        const uint4* wp = Wq + (ci * 8 * 4 + kb) * 32 + lane;
#pragma unroll
        for (int j = 0; j < 8; j++) {
            uint4 w = wp[j * 128];
            mma16(acc[j], Ah, w.x, w.y);
            mma16(acc[j], Al, w.x, w.y);
            mma16(acc[j], Ah, w.z, w.w);
        }
    }
}

__global__ __launch_bounds__(THREADS, 3)
void fused_attn_kernel(const float* __restrict__ node_feat,
                       const float* __restrict__ edge_sh,
                       const float* __restrict__ edge_inv,
                       const float* __restrict__ cutoff,
                       const float* __restrict__ W_logit,
                       const float* __restrict__ W_out,
                       const int* __restrict__ edge_src,
                       float* __restrict__ out) {
    extern __shared__ unsigned smu[];
    float* xs   = (float*)(smu + OFF_XS);
    float* qn   = (float*)(smu + OFF_QN);
    float* shm  = (float*)(smu + OFF_SH);
    float* WLs  = (float*)(smu + OFF_WL);
    float* lg   = (float*)(smu + OFF_LG);
    float* al   = (float*)(smu + OFF_AL);
    float* cw   = (float*)(smu + OFF_CW);
    float* accN = (float*)(smu + OFF_ACC);

    const int tid  = threadIdx.x;
    const int warp = tid >> 5;
    const int lane = tid & 31;
    const int gr   = lane >> 2;
    const int tig  = lane & 3;
    const int ew0  = warp * 16;
    const int n0   = blockIdx.x * GN;
    const int eg0  = blockIdx.x * EPB;

    uint4* actq = reinterpret_cast<uint4*>(smu + OFF_ACT) + warp * 256;
    unsigned* hw = smu + OFF_ACT + warp * 1024;
    unsigned* lw = hw + 512;

    // ---------- phase 0 ----------
    if (tid < EPB) cw[tid] = cutoff[eg0 + tid];
    for (int i = tid; i < 512; i += THREADS) WLs[i] = W_logit[i];
    {
        const int i2 = lane * 2;
        *reinterpret_cast<float2*>(qn + warp * 64 + i2) =
            *reinterpret_cast<const float2*>(node_feat + (n0 + warp) * 64 + i2);
    }
    {   // per-edge: 2 lanes per edge, each half the columns
        const int el   = lane >> 1;           // warp-local edge 0..15
        const int half = lane & 1;
        const int e    = ew0 + el;
        const int ge   = eg0 + e;
        const int gre  = el & 7, gr8 = el >> 3;
        *reinterpret_cast<float4*>(shm + e * 8 + half * 4) =
            *reinterpret_cast<const float4*>(edge_sh + ge * 8 + half * 4);
        const int srce = edge_src[ge];
#pragma unroll
        for (int m = 0; m < 8; m++) {
            const int c4 = half * 32 + m * 4;
            float4 v = *reinterpret_cast<const float4*>(edge_inv + ge * 64 + c4);
            act_store_c2(hw, lw, (c4 >> 1),     gre, gr8, v.x, v.y);
            act_store_c2(hw, lw, (c4 >> 1) + 1, gre, gr8, v.z, v.w);
            *reinterpret_cast<float4*>(xs + e * XSTR + c4) =
                *reinterpret_cast<const float4*>(node_feat + srce * 64 + c4);
        }
    }
    __syncthreads();

    // hoisted per-edge sh values at this thread's two columns
    const int eA = ew0 + gr, eB = ew0 + gr + 8;
    const float shvA0 = shm[eA * 8 + 2 * tig], shvA1 = shm[eA * 8 + 2 * tig + 1];
    const float shvB0 = shm[eB * 8 + 2 * tig], shvB1 = shm[eB * 8 + 2 * tig + 1];

    // ---------- key MLP layers 1,2 ----------
    layer_gemm(actq, g_Wpk + Q_K1, gr, tig, lane);
    layer_gemm(actq, g_Wpk + Q_K2, gr, tig, lane);

    // ---------- key layer-3 chunks -> logit partials ----------
    float pl[2][4];
#pragma unroll
    for (int i = 0; i < 2; i++)
#pragma unroll
        for (int h = 0; h < 4; h++) pl[i][h] = 0.f;

    const float* qrow = qn + warp * 64;

#pragma unroll 1
    for (int ci = 0; ci < 9; ci++) {
        float acc[8][4];
        chunk_gemm(actq, g_Wpk + Q_K3, ci, gr, tig, lane, acc);

        if (ci == 0) {
#pragma unroll
            for (int j = 0; j < 8; j++) {
                const int t0 = 8 * j + 2 * tig;
                float4 wl0 = *reinterpret_cast<const float4*>(WLs + t0 * 4);
                float4 wl1 = *reinterpret_cast<const float4*>(WLs + t0 * 4 + 4);
                const float q0 = qrow[t0], q1 = qrow[t0 + 1];
                float cA0 = q0 * xs[eA * XSTR + t0]     * acc[j][0];
                float cA1 = q1 * xs[eA * XSTR + t0 + 1] * acc[j][1];
                float cB0 = q0 * xs[eB * XSTR + t0]     * acc[j][2];
                float cB1 = q1 * xs[eB * XSTR + t0 + 1] * acc[j][3];
                pl[0][0] += cA0 * wl0.x + cA1 * wl1.x;
                pl[0][1] += cA0 * wl0.y + cA1 * wl1.y;
                pl[0][2] += cA0 * wl0.z + cA1 * wl1.z;
                pl[0][3] += cA0 * wl0.w + cA1 * wl1.w;
                pl[1][0] += cB0 * wl0.x + cB1 * wl1.x;
                pl[1][1] += cB0 * wl0.y + cB1 * wl1.y;
                pl[1][2] += cB0 * wl0.z + cB1 * wl1.z;
                pl[1][3] += cB0 * wl0.w + cB1 * wl1.w;
            }
        } else {
#pragma unroll
            for (int j = 0; j < 8; j++) {
                const int d = 8 * (ci - 1) + j;
                float4 wl = *reinterpret_cast<const float4*>(WLs + (64 + d) * 4);
                const float qd = qrow[d];
                float cA = qd * xs[eA * XSTR + d] *
                           (shvA0 * shvA0 * acc[j][0] + shvA1 * shvA1 * acc[j][1]);
                float cB = qd * xs[eB * XSTR + d] *
                           (shvB0 * shvB0 * acc[j][2] + shvB1 * shvB1 * acc[j][3]);
                pl[0][0] += cA * wl.x; pl[0][1] += cA * wl.y;
                pl[0][2] += cA * wl.z; pl[0][3] += cA * wl.w;
                pl[1][0] += cB * wl.x; pl[1][1] += cB * wl.y;
                pl[1][2] += cB * wl.z; pl[1][3] += cB * wl.w;
            }
        }
    }

    // reduce pl over the 4 tig lanes; tig==0 stores
#pragma unroll
    for (int msk = 1; msk < 4; msk <<= 1)
#pragma unroll
        for (int i = 0; i < 2; i++)
#pragma unroll
            for (int h = 0; h < 4; h++)
                pl[i][h] += __shfl_xor_sync(0xffffffffu, pl[i][h], msk);
    if (tig == 0) {
        *reinterpret_cast<float4*>(lg + eA * 4) =
            make_float4(pl[0][0], pl[0][1], pl[0][2], pl[0][3]);
        *reinterpret_cast<float4*>(lg + eB * 4) =
            make_float4(pl[1][0], pl[1][1], pl[1][2], pl[1][3]);
    }
    __syncwarp();

    // reload edge_inv split into act (warp-local rows)
    {
        const int el   = lane >> 1;
        const int half = lane & 1;
        const int ge   = eg0 + ew0 + el;
        const int gre  = el & 7, gr8 = el >> 3;
#pragma unroll
        for (int m = 0; m < 8; m++) {
            const int c4 = half * 32 + m * 4;
            float4 v = *reinterpret_cast<const float4*>(edge_inv + ge * 64 + c4);
            act_store_c2(hw, lw, (c4 >> 1),     gre, gr8, v.x, v.y);
            act_store_c2(hw, lw, (c4 >> 1) + 1, gre, gr8, v.z, v.w);
        }
    }
    __syncthreads();   // lg visible to warp 0

    // ---------- softmax ----------
    if (tid < GN * HHEAD) {
        const int n = tid >> 2, h = tid & 3;
        float mx = -3.0e38f;
        for (int j = 0; j < KEDGE; j++)
            mx = fmaxf(mx, lg[(n * KEDGE + j) * 4 + h]);
        float z = 0.f;
        float ex[KEDGE];
        for (int j = 0; j < KEDGE; j++) {
            const int e = n * KEDGE + j;
            ex[j] = cw[e] * expf(lg[e * 4 + h] - mx);
            z += ex[j];
        }
        if (z == 0.f) z = 1.f;
        const float inv = 1.f / z;
        for (int j = 0; j < KEDGE; j++)
            al[(n * KEDGE + j) * 4 + h] = sqrtf(ex[j] * inv);
    }

    // ---------- value MLP layers 1,2 (independent of al) ----------
    layer_gemm(actq, g_Wpk + Q_V1, gr, tig, lane);
    layer_gemm(actq, g_Wpk + Q_V2, gr, tig, lane);
    __syncthreads();   // al visible

    // ---------- value layer-3 chunks -> node accumulators ----------
#pragma unroll 1
    for (int ci = 0; ci < 9; ci++) {
        float acc[8][4];
        chunk_gemm(actq, g_Wpk + Q_V3, ci, gr, tig, lane, acc);

        float pk[8][2];
        if (ci == 0) {
            const float aA = al[eA * 4], aB = al[eB * 4];
#pragma unroll
            for (int j = 0; j < 8; j++) {
                const int t0 = 8 * j + 2 * tig;
                pk[j][0] = xs[eA * XSTR + t0]     * acc[j][0] * aA
                         + xs[eB * XSTR + t0]     * acc[j][2] * aB;
                pk[j][1] = xs[eA * XSTR + t0 + 1] * acc[j][1] * aA
                         + xs[eB * XSTR + t0 + 1] * acc[j][3] * aB;
            }
        } else {
#pragma unroll
            for (int j = 0; j < 8; j++) {
                const int d  = 8 * (ci - 1) + j;
                const int C0 = ci * 64 + 8 * j + 2 * tig;
                const int h0 = C0 / FPH, h1 = (C0 + 1) / FPH;
                const float xA = xs[eA * XSTR + d], xB = xs[eB * XSTR + d];
                pk[j][0] = xA * shvA0 * acc[j][0] * al[eA * 4 + h0]
                         + xB * shvB0 * acc[j][2] * al[eB * 4 + h0];
                pk[j][1] = xA * shvA1 * acc[j][1] * al[eA * 4 + h1]
                         + xB * shvB1 * acc[j][3] * al[eB * 4 + h1];
            }
        }
#pragma unroll
        for (int j = 0; j < 8; j++)
#pragma unroll
            for (int p = 0; p < 2; p++) {
                pk[j][p] += __shfl_xor_sync(0xffffffffu, pk[j][p], 4);
                pk[j][p] += __shfl_xor_sync(0xffffffffu, pk[j][p], 8);
                pk[j][p] += __shfl_xor_sync(0xffffffffu, pk[j][p], 16);
            }
        if (gr == 0) {
#pragma unroll
            for (int j = 0; j < 8; j++)
                *reinterpret_cast<float2*>(accN + warp * FDIM + ci * 64 + 8 * j + 2 * tig) =
                    make_float2(pk[j][0], pk[j][1]);
        }
    }
    __syncthreads();   // accN complete; act region free as scratch

    // ---------- epilogue: out[n] = accN[n] @ W_out (576x64), c-split halves ----------
    {
        const int dcol = tid & 63;
        const int half = tid >> 6;
        const int cbeg = half * 288;
        float s[4] = {0.f, 0.f, 0.f, 0.f};
        for (int c = cbeg; c < cbeg + 288; c += 4) {
            float w0 = W_out[(c + 0) * 64 + dcol];
            float w1 = W_out[(c + 1) * 64 + dcol];
            float w2 = W_out[(c + 2) * 64 + dcol];
            float w3 = W_out[(c + 3) * 64 + dcol];
#pragma unroll
            for (int n = 0; n < 4; n++) {
                float4 a = *reinterpret_cast<const float4*>(accN + n * FDIM + c);
                s[n] += a.x * w0 + a.y * w1 + a.z * w2 + a.w * w3;
            }
        }
        float* scratch = (float*)(smu + OFF_ACT);
        if (half == 1) {
#pragma unroll
            for (int n = 0; n < 4; n++) scratch[n * 64 + dcol] = s[n];
        }
        __syncthreads();
        if (half == 0) {
#pragma unroll
            for (int n = 0; n < 4; n++)
                out[(n0 + n) * 64 + dcol] = s[n] + scratch[n * 64 + dcol];
        }
    }
}

extern "C" void kernel_launch(void* const* d_in, const int* in_sizes, int n_in,
                              void* d_out, int out_size) {
    const float* node_feat = (const float*)d_in[0];
    const float* edge_sh   = (const float*)d_in[1];
    const float* edge_inv  = (const float*)d_in[2];
    const float* cutoff    = (const float*)d_in[3];
    const float* Wk1       = (const float*)d_in[4];
    const float* Wk2       = (const float*)d_in[5];
    const float* Wk3       = (const float*)d_in[6];
    const float* Wv1       = (const float*)d_in[7];
    const float* Wv2       = (const float*)d_in[8];
    const float* Wv3       = (const float*)d_in[9];
    const float* W_logit   = (const float*)d_in[10];
    const float* W_out     = (const float*)d_in[11];
    const int*   edge_src  = (const int*)d_in[12];
    float* out = (float*)d_out;

    prep_kernel<<<(Q_TOTAL + 255) / 256, 256>>>(Wk1, Wk2, Wk3, Wv1, Wv2, Wv3);

    size_t smem = SMEM_U32 * 4;
    cudaFuncSetAttribute(fused_attn_kernel,
                         cudaFuncAttributeMaxDynamicSharedMemorySize, (int)smem);
    fused_attn_kernel<<<NNODES / GN, THREADS, smem>>>(
        node_feat, edge_sh, edge_inv, cutoff,
        W_logit, W_out, edge_src, out);
}

// round 10
// speedup vs baseline: 6.0246x; 1.0002x over previous
#include <cuda_runtime.h>
#include <math.h>

// Problem constants
#define KEDGE   16
#define SDIM    8
#define HHEAD   4
#define FDIM    576
#define FPH     144
#define NNODES  8192

// Tiling: 8 nodes (128 edges) per block, 4 warps, warp = 32 edges = 2 m16 atoms
#define GN      8
#define EPB     128
#define THREADS 128
#define XSTR    68    // xs row stride (f32)

// smem offsets (u32 units)
// act: warp w -> u32 [w*2048, (w+1)*2048); atom m at +m*1024 (hi 512, lo 512)
//   quad(c2, gr) = ((c2>>3)*4 + (c2&3))*8 + gr ; word = quad*4 + ((c2>>2)&1)*2 + gr8
#define OFF_ACT 0                       // 8192 u32 (32 KB)
#define OFF_XS  8192                    // [128][68] f32
#define OFF_QN  (OFF_XS + EPB*XSTR)     // [8][64]
#define OFF_SH  (OFF_QN + GN*64)        // [128][8]
#define OFF_WL  (OFF_SH + EPB*SDIM)     // [128][4]
#define OFF_LG  (OFF_WL + 512)          // [128][4]
#define OFF_AL  (OFF_LG + EPB*4)        // [128][4]
#define OFF_CW  (OFF_AL + EPB*4)        // [128]
#define OFF_ACC (OFF_CW + EPB)          // [8][576]
#define SMEM_U32 (OFF_ACC + GN*FDIM)    // 24704 u32 = 98816 B -> 2 CTAs/SM

// ---- fragment-ordered packed weights: uint4 {b0h, b1h, b0l, b1l} ----
#define Q_K1 0          // 64x64 -> 1024 uint4
#define Q_K2 1024
#define Q_V1 2048
#define Q_V2 3072
#define Q_K3 4096       // 64x576 -> 9216 uint4
#define Q_V3 13312
#define Q_TOTAL 22528
__device__ uint4 g_Wpk[Q_TOTAL];

__device__ __forceinline__ unsigned pack_bf16x2(float v_odd, float v_even) {
    unsigned r;
    asm("cvt.rn.bf16x2.f32 %0, %1, %2;" : "=r"(r) : "f"(v_odd), "f"(v_even));
    return r;
}
__device__ __forceinline__ float bf_lo_f(unsigned u) { return __uint_as_float(u << 16); }
__device__ __forceinline__ float bf_hi_f(unsigned u) { return __uint_as_float(u & 0xffff0000u); }

__device__ __forceinline__ void mma16(float c[4], const unsigned a[4],
                                      unsigned b0, unsigned b1) {
    asm("mma.sync.aligned.m16n8k16.row.col.f32.bf16.bf16.f32 "
        "{%0,%1,%2,%3}, {%4,%5,%6,%7}, {%8,%9}, {%0,%1,%2,%3};"
        : "+f"(c[0]), "+f"(c[1]), "+f"(c[2]), "+f"(c[3])
        : "r"(a[0]), "r"(a[1]), "r"(a[2]), "r"(a[3]), "r"(b0), "r"(b1));
}

__device__ __forceinline__ float gelu_f(float x) {
    float u = 0.7978845608028654f * (x + 0.044715f * x * x * x);
    float t;
    asm("tanh.approx.f32 %0, %1;" : "=f"(t) : "f"(u));
    return 0.5f * x * (1.0f + t);
}

__global__ void prep_kernel(const float* __restrict__ Wk1, const float* __restrict__ Wk2,
                            const float* __restrict__ Wk3, const float* __restrict__ Wv1,
                            const float* __restrict__ Wv2, const float* __restrict__ Wv3) {
    int i = blockIdx.x * 256 + threadIdx.x;
    if (i >= Q_TOTAL) return;
    const float* src; int ncols, q;
    if      (i < Q_K2) { src = Wk1; ncols = 64;  q = i - Q_K1; }
    else if (i < Q_V1) { src = Wk2; ncols = 64;  q = i - Q_K2; }
    else if (i < Q_V2) { src = Wv1; ncols = 64;  q = i - Q_V1; }
    else if (i < Q_K3) { src = Wv2; ncols = 64;  q = i - Q_V2; }
    else if (i < Q_V3) { src = Wk3; ncols = 576; q = i - Q_K3; }
    else               { src = Wv3; ncols = 576; q = i - Q_V3; }
    const int jblk = q >> 7;
    const int kb   = (q >> 5) & 3;
    const int lane = q & 31;
    const int gr   = lane >> 2;
    const int tig  = lane & 3;
    const int n    = jblk * 8 + gr;
    const int kA   = 2 * (kb * 8 + tig);
    const int kB   = 2 * (kb * 8 + tig + 4);
    float a0 = src[kA * ncols + n],       a1 = src[(kA + 1) * ncols + n];
    float b0 = src[kB * ncols + n],       b1 = src[(kB + 1) * ncols + n];
    unsigned h0 = pack_bf16x2(a1, a0);
    unsigned h1 = pack_bf16x2(b1, b0);
    unsigned l0 = pack_bf16x2(a1 - bf_hi_f(h0), a0 - bf_lo_f(h0));
    unsigned l1 = pack_bf16x2(b1 - bf_hi_f(h1), b0 - bf_lo_f(h1));
    uint4 o; o.x = h0; o.y = h1; o.z = l0; o.w = l1;
    g_Wpk[i] = o;
}

// write one (c2) column-pair for an edge into its atom's fragment-quad layout
__device__ __forceinline__ void act_store_c2(unsigned* hw, unsigned* lw,
                                             int c2, int gr_e, int gr8,
                                             float v0, float v1) {
    unsigned h = pack_bf16x2(v1, v0);
    unsigned l = pack_bf16x2(v1 - bf_hi_f(h), v0 - bf_lo_f(h));
    const int quad = ((c2 >> 3) * 4 + (c2 & 3)) * 8 + gr_e;
    const int idx  = quad * 4 + ((c2 >> 2) & 1) * 2 + gr8;
    hw[idx] = h;
    lw[idx] = l;
}

// 32x64x64 layer GEMM (2 atoms), in-place gelu+split store.
// actq = warp's uint4 base (512 uint4: atom m at +m*256; hi 128, lo 128)
__device__ __forceinline__ void layer_gemm(uint4* actq, const uint4* __restrict__ Wq,
                                           int gr, int tig, int lane) {
    float acc[2][8][4];
#pragma unroll
    for (int m = 0; m < 2; m++)
#pragma unroll
        for (int j = 0; j < 8; j++)
#pragma unroll
            for (int p = 0; p < 4; p++) acc[m][j][p] = 0.f;

#pragma unroll
    for (int kb = 0; kb < 4; kb++) {
        const int qi = (kb * 4 + tig) * 8 + gr;
        uint4 ah0 = actq[qi],        al0 = actq[128 + qi];
        uint4 ah1 = actq[256 + qi],  al1 = actq[384 + qi];
        unsigned Ah[2][4] = {{ah0.x, ah0.y, ah0.z, ah0.w}, {ah1.x, ah1.y, ah1.z, ah1.w}};
        unsigned Al[2][4] = {{al0.x, al0.y, al0.z, al0.w}, {al1.x, al1.y, al1.z, al1.w}};
        const uint4* wp = Wq + kb * 32 + lane;
#pragma unroll
        for (int j = 0; j < 8; j++) {
            uint4 w = wp[j * 128];
#pragma unroll
            for (int m = 0; m < 2; m++) {
                mma16(acc[m][j], Ah[m], w.x, w.y);
                mma16(acc[m][j], Al[m], w.x, w.y);
                mma16(acc[m][j], Ah[m], w.z, w.w);
            }
        }
    }
    __syncwarp();
#pragma unroll
    for (int m = 0; m < 2; m++) {
        unsigned* hw = (unsigned*)actq + m * 1024;
        unsigned* lw = hw + 512;
#pragma unroll
        for (int j = 0; j < 8; j++) {
            float g0 = gelu_f(acc[m][j][0]), g1 = gelu_f(acc[m][j][1]);
            float g2 = gelu_f(acc[m][j][2]), g3 = gelu_f(acc[m][j][3]);
            unsigned hA = pack_bf16x2(g1, g0);
            unsigned hB = pack_bf16x2(g3, g2);
            unsigned lA = pack_bf16x2(g1 - bf_hi_f(hA), g0 - bf_lo_f(hA));
            unsigned lB = pack_bf16x2(g3 - bf_hi_f(hB), g2 - bf_lo_f(hB));
            const int c2   = j * 4 + tig;
            const int quad = ((c2 >> 3) * 4 + (c2 & 3)) * 8 + gr;
            const int base = quad * 4 + ((c2 >> 2) & 1) * 2;
            *reinterpret_cast<uint2*>(hw + base) = make_uint2(hA, hB);
            *reinterpret_cast<uint2*>(lw + base) = make_uint2(lA, lB);
        }
    }
    __syncwarp();
}

// 32x64 chunk of a 64x576 layer-3 GEMM; acc left in registers.
__device__ __forceinline__ void chunk_gemm(const uint4* actq, const uint4* __restrict__ Wq,
                                           int ci, int gr, int tig, int lane,
                                           float acc[2][8][4]) {
#pragma unroll
    for (int m = 0; m < 2; m++)
#pragma unroll
        for (int j = 0; j < 8; j++)
#pragma unroll
            for (int p = 0; p < 4; p++) acc[m][j][p] = 0.f;

#pragma unroll
    for (int kb = 0; kb < 4; kb++) {
        const int qi = (kb * 4 + tig) * 8 + gr;
        uint4 ah0 = actq[qi],        al0 = actq[128 + qi];
        uint4 ah1 = actq[256 + qi],  al1 = actq[384 + qi];
        unsigned Ah[2][4] = {{ah0.x, ah0.y, ah0.z, ah0.w}, {ah1.x, ah1.y, ah1.z, ah1.w}};
        unsigned Al[2][4] = {{al0.x, al0.y, al0.z, al0.w}, {al1.x, al1.y, al1.z, al1.w}};
        const uint4* wp = Wq + (ci * 32 + kb) * 32 + lane;
#pragma unroll
        for (int j = 0; j < 8; j++) {
            uint4 w = wp[j * 128];
#pragma unroll
            for (int m = 0; m < 2; m++) {
                mma16(acc[m][j], Ah[m], w.x, w.y);
                mma16(acc[m][j], Al[m], w.x, w.y);
                mma16(acc[m][j], Ah[m], w.z, w.w);
            }
        }
    }
}

__global__ __launch_bounds__(THREADS, 2)
void fused_attn_kernel(const float* __restrict__ node_feat,
                       const float* __restrict__ edge_sh,
                       const float* __restrict__ edge_inv,
                       const float* __restrict__ cutoff,
                       const float* __restrict__ W_logit,
                       const float* __restrict__ W_out,
                       const int* __restrict__ edge_src,
                       float* __restrict__ out) {
    extern __shared__ unsigned smu[];
    float* xs   = (float*)(smu + OFF_XS);
    float* qn   = (float*)(smu + OFF_QN);
    float* shm  = (float*)(smu + OFF_SH);
    float* WLs  = (float*)(smu + OFF_WL);
    float* lg   = (float*)(smu + OFF_LG);
    float* al   = (float*)(smu + OFF_AL);
    float* cw   = (float*)(smu + OFF_CW);
    float* accN = (float*)(smu + OFF_ACC);

    const int tid  = threadIdx.x;
    const int warp = tid >> 5;
    const int lane = tid & 31;
    const int gr   = lane >> 2;
    const int tig  = lane & 3;
    const int ew0  = warp * 32;
    const int n0   = blockIdx.x * GN;
    const int eg0  = blockIdx.x * EPB;

    uint4* actq = reinterpret_cast<uint4*>(smu + OFF_ACT) + warp * 512;

    // ---------- phase 0 ----------
    cw[tid] = cutoff[eg0 + tid];
    for (int i = tid; i < 512; i += THREADS) WLs[i] = W_logit[i];
    for (int i = tid; i < GN * 64; i += THREADS) qn[i] = node_feat[n0 * 64 + i];
    {   // lane = one edge of this warp (32 edges)
        const int el = lane;
        const int m  = el >> 4;
        const int e16 = el & 15;
        const int gre = e16 & 7, gr8 = e16 >> 3;
        unsigned* hw_e = smu + OFF_ACT + warp * 2048 + m * 1024;
        unsigned* lw_e = hw_e + 512;
        const int e  = ew0 + el;
        const int ge = eg0 + e;
        *reinterpret_cast<float4*>(shm + e * 8) =
            *reinterpret_cast<const float4*>(edge_sh + ge * 8);
        *reinterpret_cast<float4*>(shm + e * 8 + 4) =
            *reinterpret_cast<const float4*>(edge_sh + ge * 8 + 4);
        const int srce = edge_src[ge];
#pragma unroll
        for (int m4 = 0; m4 < 16; m4++) {
            const int c4 = m4 * 4;
            float4 v = *reinterpret_cast<const float4*>(edge_inv + ge * 64 + c4);
            act_store_c2(hw_e, lw_e, (c4 >> 1),     gre, gr8, v.x, v.y);
            act_store_c2(hw_e, lw_e, (c4 >> 1) + 1, gre, gr8, v.z, v.w);
            *reinterpret_cast<float4*>(xs + e * XSTR + c4) =
                *reinterpret_cast<const float4*>(node_feat + srce * 64 + c4);
        }
    }
    __syncthreads();

    // hoisted per-edge sh values at this thread's two columns (per atom)
    float shv0[2][2], shv1[2][2];   // [m][A/B]
#pragma unroll
    for (int m = 0; m < 2; m++) {
        const int eA = ew0 + 16 * m + gr, eB = eA + 8;
        shv0[m][0] = shm[eA * 8 + 2 * tig]; shv1[m][0] = shm[eA * 8 + 2 * tig + 1];
        shv0[m][1] = shm[eB * 8 + 2 * tig]; shv1[m][1] = shm[eB * 8 + 2 * tig + 1];
    }

    // ---------- key MLP layers 1,2 ----------
    layer_gemm(actq, g_Wpk + Q_K1, gr, tig, lane);
    layer_gemm(actq, g_Wpk + Q_K2, gr, tig, lane);

    // ---------- key layer-3 chunks -> logit partials ----------
    float pl[2][2][4];   // [m][A/B][h]
#pragma unroll
    for (int m = 0; m < 2; m++)
#pragma unroll
        for (int i = 0; i < 2; i++)
#pragma unroll
            for (int h = 0; h < 4; h++) pl[m][i][h] = 0.f;

#pragma unroll 1
    for (int ci = 0; ci < 9; ci++) {
        float acc[2][8][4];
        chunk_gemm(actq, g_Wpk + Q_K3, ci, gr, tig, lane, acc);

        if (ci == 0) {
#pragma unroll
            for (int j = 0; j < 8; j++) {
                const int t0 = 8 * j + 2 * tig;
                float4 wl0 = *reinterpret_cast<const float4*>(WLs + t0 * 4);
                float4 wl1 = *reinterpret_cast<const float4*>(WLs + t0 * 4 + 4);
#pragma unroll
                for (int m = 0; m < 2; m++) {
                    const float* qrow = qn + (2 * warp + m) * 64;
                    const float q0 = qrow[t0], q1 = qrow[t0 + 1];
                    const int eA = ew0 + 16 * m + gr, eB = eA + 8;
                    float cA0 = q0 * xs[eA * XSTR + t0]     * acc[m][j][0];
                    float cA1 = q1 * xs[eA * XSTR + t0 + 1] * acc[m][j][1];
                    float cB0 = q0 * xs[eB * XSTR + t0]     * acc[m][j][2];
                    float cB1 = q1 * xs[eB * XSTR + t0 + 1] * acc[m][j][3];
                    pl[m][0][0] += cA0 * wl0.x + cA1 * wl1.x;
                    pl[m][0][1] += cA0 * wl0.y + cA1 * wl1.y;
                    pl[m][0][2] += cA0 * wl0.z + cA1 * wl1.z;
                    pl[m][0][3] += cA0 * wl0.w + cA1 * wl1.w;
                    pl[m][1][0] += cB0 * wl0.x + cB1 * wl1.x;
                    pl[m][1][1] += cB0 * wl0.y + cB1 * wl1.y;
                    pl[m][1][2] += cB0 * wl0.z + cB1 * wl1.z;
                    pl[m][1][3] += cB0 * wl0.w + cB1 * wl1.w;
                }
            }
        } else {
#pragma unroll
            for (int j = 0; j < 8; j++) {
                const int d = 8 * (ci - 1) + j;
                float4 wl = *reinterpret_cast<const float4*>(WLs + (64 + d) * 4);
#pragma unroll
                for (int m = 0; m < 2; m++) {
                    const float qd = qn[(2 * warp + m) * 64 + d];
                    const int eA = ew0 + 16 * m + gr, eB = eA + 8;
                    float cA = qd * xs[eA * XSTR + d] *
                               (shv0[m][0] * shv0[m][0] * acc[m][j][0] +
                                shv1[m][0] * shv1[m][0] * acc[m][j][1]);
                    float cB = qd * xs[eB * XSTR + d] *
                               (shv0[m][1] * shv0[m][1] * acc[m][j][2] +
                                shv1[m][1] * shv1[m][1] * acc[m][j][3]);
                    pl[m][0][0] += cA * wl.x; pl[m][0][1] += cA * wl.y;
                    pl[m][0][2] += cA * wl.z; pl[m][0][3] += cA * wl.w;
                    pl[m][1][0] += cB * wl.x; pl[m][1][1] += cB * wl.y;
                    pl[m][1][2] += cB * wl.z; pl[m][1][3] += cB * wl.w;
                }
            }
        }
    }

    // reduce pl over the 4 tig lanes; tig==0 stores
#pragma unroll
    for (int msk = 1; msk < 4; msk <<= 1)
#pragma unroll
        for (int m = 0; m < 2; m++)
#pragma unroll
            for (int i = 0; i < 2; i++)
#pragma unroll
                for (int h = 0; h < 4; h++)
                    pl[m][i][h] += __shfl_xor_sync(0xffffffffu, pl[m][i][h], msk);
    if (tig == 0) {
#pragma unroll
        for (int m = 0; m < 2; m++) {
            const int eA = ew0 + 16 * m + gr, eB = eA + 8;
            *reinterpret_cast<float4*>(lg + eA * 4) =
                make_float4(pl[m][0][0], pl[m][0][1], pl[m][0][2], pl[m][0][3]);
            *reinterpret_cast<float4*>(lg + eB * 4) =
                make_float4(pl[m][1][0], pl[m][1][1], pl[m][1][2], pl[m][1][3]);
        }
    }
    __syncwarp();

    // reload edge_inv split into act (warp-local rows)
    {
        const int el = lane;
        const int m  = el >> 4;
        const int e16 = el & 15;
        const int gre = e16 & 7, gr8 = e16 >> 3;
        unsigned* hw_e = smu + OFF_ACT + warp * 2048 + m * 1024;
        unsigned* lw_e = hw_e + 512;
        const int ge = eg0 + ew0 + el;
#pragma unroll
        for (int m4 = 0; m4 < 16; m4++) {
            const int c4 = m4 * 4;
            float4 v = *reinterpret_cast<const float4*>(edge_inv + ge * 64 + c4);
            act_store_c2(hw_e, lw_e, (c4 >> 1),     gre, gr8, v.x, v.y);
            act_store_c2(hw_e, lw_e, (c4 >> 1) + 1, gre, gr8, v.z, v.w);
        }
    }
    __syncthreads();   // lg visible

    // ---------- softmax ----------
    if (tid < GN * HHEAD) {
        const int n = tid >> 2, h = tid & 3;
        float mx = -3.0e38f;
        for (int j = 0; j < KEDGE; j++)
            mx = fmaxf(mx, lg[(n * KEDGE + j) * 4 + h]);
        float z = 0.f;
        float ex[KEDGE];
        for (int j = 0; j < KEDGE; j++) {
            const int e = n * KEDGE + j;
            ex[j] = cw[e] * expf(lg[e * 4 + h] - mx);
            z += ex[j];
        }
        if (z == 0.f) z = 1.f;
        const float inv = 1.f / z;
        for (int j = 0; j < KEDGE; j++)
            al[(n * KEDGE + j) * 4 + h] = sqrtf(ex[j] * inv);
    }

    // ---------- value MLP layers 1,2 ----------
    layer_gemm(actq, g_Wpk + Q_V1, gr, tig, lane);
    layer_gemm(actq, g_Wpk + Q_V2, gr, tig, lane);
    __syncthreads();   // al visible

    // ---------- value layer-3 chunks -> node accumulators ----------
#pragma unroll 1
    for (int ci = 0; ci < 9; ci++) {
        float acc[2][8][4];
        chunk_gemm(actq, g_Wpk + Q_V3, ci, gr, tig, lane, acc);

        float pk[2][8][2];
        if (ci == 0) {
#pragma unroll
            for (int m = 0; m < 2; m++) {
                const int eA = ew0 + 16 * m + gr, eB = eA + 8;
                const float aA = al[eA * 4], aB = al[eB * 4];
#pragma unroll
                for (int j = 0; j < 8; j++) {
                    const int t0 = 8 * j + 2 * tig;
                    pk[m][j][0] = xs[eA * XSTR + t0]     * acc[m][j][0] * aA
                                + xs[eB * XSTR + t0]     * acc[m][j][2] * aB;
                    pk[m][j][1] = xs[eA * XSTR + t0 + 1] * acc[m][j][1] * aA
                                + xs[eB * XSTR + t0 + 1] * acc[m][j][3] * aB;
                }
            }
        } else {
#pragma unroll
            for (int j = 0; j < 8; j++) {
                const int d  = 8 * (ci - 1) + j;
                const int C0 = ci * 64 + 8 * j + 2 * tig;
                const int h0 = C0 / FPH, h1 = (C0 + 1) / FPH;
#pragma unroll
                for (int m = 0; m < 2; m++) {
                    const int eA = ew0 + 16 * m + gr, eB = eA + 8;
                    const float xA = xs[eA * XSTR + d], xB = xs[eB * XSTR + d];
                    pk[m][j][0] = xA * shv0[m][0] * acc[m][j][0] * al[eA * 4 + h0]
                                + xB * shv0[m][1] * acc[m][j][2] * al[eB * 4 + h0];
                    pk[m][j][1] = xA * shv1[m][0] * acc[m][j][1] * al[eA * 4 + h1]
                                + xB * shv1[m][1] * acc[m][j][3] * al[eB * 4 + h1];
                }
            }
        }
#pragma unroll
        for (int m = 0; m < 2; m++)
#pragma unroll
            for (int j = 0; j < 8; j++)
#pragma unroll
                for (int p = 0; p < 2; p++) {
                    pk[m][j][p] += __shfl_xor_sync(0xffffffffu, pk[m][j][p], 4);
                    pk[m][j][p] += __shfl_xor_sync(0xffffffffu, pk[m][j][p], 8);
                    pk[m][j][p] += __shfl_xor_sync(0xffffffffu, pk[m][j][p], 16);
                }
        if (gr == 0) {
#pragma unroll
            for (int m = 0; m < 2; m++)
#pragma unroll
                for (int j = 0; j < 8; j++)
                    *reinterpret_cast<float2*>(
                        accN + (2 * warp + m) * FDIM + ci * 64 + 8 * j + 2 * tig) =
                        make_float2(pk[m][j][0], pk[m][j][1]);
        }
    }
    __syncthreads();   // accN complete; act region free as scratch

    // ---------- epilogue: out[n] = accN[n] @ W_out (576x64), c-split halves ----------
    {
        const int dcol = tid & 63;
        const int half = tid >> 6;
        const int cbeg = half * 288;
        float s[8] = {0.f, 0.f, 0.f, 0.f, 0.f, 0.f, 0.f, 0.f};
        for (int c = cbeg; c < cbeg + 288; c += 4) {
            float w0 = W_out[(c + 0) * 64 + dcol];
            float w1 = W_out[(c + 1) * 64 + dcol];
            float w2 = W_out[(c + 2) * 64 + dcol];
            float w3 = W_out[(c + 3) * 64 + dcol];
#pragma unroll
            for (int n = 0; n < 8; n++) {
                float4 a = *reinterpret_cast<const float4*>(accN + n * FDIM + c);
                s[n] += a.x * w0 + a.y * w1 + a.z * w2 + a.w * w3;
            }
        }
        float* scratch = (float*)(smu + OFF_ACT);
        if (half == 1) {
#pragma unroll
            for (int n = 0; n < 8; n++) scratch[n * 64 + dcol] = s[n];
        }
        __syncthreads();
        if (half == 0) {
#pragma unroll
            for (int n = 0; n < 8; n++)
                out[(n0 + n) * 64 + dcol] = s[n] + scratch[n * 64 + dcol];
        }
    }
}

extern "C" void kernel_launch(void* const* d_in, const int* in_sizes, int n_in,
                              void* d_out, int out_size) {
    const float* node_feat = (const float*)d_in[0];
    const float* edge_sh   = (const float*)d_in[1];
    const float* edge_inv  = (const float*)d_in[2];
    const float* cutoff    = (const float*)d_in[3];
    const float* Wk1       = (const float*)d_in[4];
    const float* Wk2       = (const float*)d_in[5];
    const float* Wk3       = (const float*)d_in[6];
    const float* Wv1       = (const float*)d_in[7];
    const float* Wv2       = (const float*)d_in[8];
    const float* Wv3       = (const float*)d_in[9];
    const float* W_logit   = (const float*)d_in[10];
    const float* W_out     = (const float*)d_in[11];
    const int*   edge_src  = (const int*)d_in[12];
    float* out = (float*)d_out;

    prep_kernel<<<(Q_TOTAL + 255) / 256, 256>>>(Wk1, Wk2, Wk3, Wv1, Wv2, Wv3);

    size_t smem = SMEM_U32 * 4;
    cudaFuncSetAttribute(fused_attn_kernel,
                         cudaFuncAttributeMaxDynamicSharedMemorySize, (int)smem);
    fused_attn_kernel<<<NNODES / GN, THREADS, smem>>>(
        node_feat, edge_sh, edge_inv, cutoff,
        W_logit, W_out, edge_src, out);
}